// round 5
// baseline (speedup 1.0000x reference)
#include <cuda_runtime.h>
#include <stdint.h>

#define B_N    2048
#define D_N    1024
#define POOL_N 2048
#define HARD_N 128
#define EXTRA_N 64
#define AFIN_N 256   /* padded; 192 real columns */
#define NFIN   192

/* ------------------------------------------------------------------ */
/* Scratch (static device globals; no allocation anywhere)            */
/* ------------------------------------------------------------------ */
__device__ float  g_Apool[D_N * POOL_N];   /* (D, POOL) row-major       */
__device__ float  g_zc[B_N * D_N];         /* centered z                */
__device__ float  g_means[D_N];
__device__ float  g_ut[POOL_N * B_N];      /* u^T (pool x B)            */
__device__ float  g_u2t[AFIN_N * B_N];     /* u2^T (256 x B)            */
__device__ double g_losses[POOL_N];
__device__ int    g_ranked[HARD_N];
__device__ float  g_Q[HARD_N * D_N];       /* col i at i*1024           */
__device__ float  g_R[D_N * EXTRA_N];      /* (D, EXTRA) row-major      */
__device__ float  g_C[HARD_N * EXTRA_N];
__device__ float  g_Afin[D_N * AFIN_N];    /* (D, 256) row-major        */
__device__ double g_floss[NFIN];

/* ------------------------------------------------------------------ */
/* JAX threefry2x32 (20 rounds)                                       */
/* ------------------------------------------------------------------ */
__device__ __forceinline__ uint32_t rotl32(uint32_t x, int r) {
    return (x << r) | (x >> (32 - r));
}

__device__ __forceinline__ void threefry2x32(uint32_t k0, uint32_t k1,
                                             uint32_t x0, uint32_t x1,
                                             uint32_t& o0, uint32_t& o1) {
    uint32_t ks2 = k0 ^ k1 ^ 0x1BD11BDAu;
    x0 += k0; x1 += k1;
#define TFR(r) { x0 += x1; x1 = rotl32(x1, (r)); x1 ^= x0; }
    TFR(13) TFR(15) TFR(26) TFR(6)  x0 += k1;  x1 += ks2 + 1u;
    TFR(17) TFR(29) TFR(16) TFR(24) x0 += ks2; x1 += k0  + 2u;
    TFR(13) TFR(15) TFR(26) TFR(6)  x0 += k0;  x1 += k1  + 3u;
    TFR(17) TFR(29) TFR(16) TFR(24) x0 += k1;  x1 += ks2 + 4u;
    TFR(13) TFR(15) TFR(26) TFR(6)  x0 += ks2; x1 += k0  + 5u;
#undef TFR
    o0 = x0; o1 = x1;
}

/* XLA ErfInv32: w = -log1p(-x*x), Giles polynomial */
__device__ __forceinline__ float erfinv_xla(float x) {
    float w = -log1pf(-x * x);
    float p;
    if (w < 5.0f) {
        w -= 2.5f;
        p = 2.81022636e-08f;
        p = fmaf(p, w, 3.43273939e-07f);
        p = fmaf(p, w, -3.5233877e-06f);
        p = fmaf(p, w, -4.39150654e-06f);
        p = fmaf(p, w, 0.00021858087f);
        p = fmaf(p, w, -0.00125372503f);
        p = fmaf(p, w, -0.00417768164f);
        p = fmaf(p, w, 0.246640727f);
        p = fmaf(p, w, 1.50140941f);
    } else {
        w = sqrtf(w) - 3.0f;
        p = -0.000200214257f;
        p = fmaf(p, w, 0.000100950558f);
        p = fmaf(p, w, 0.00134934322f);
        p = fmaf(p, w, -0.00367342844f);
        p = fmaf(p, w, 0.00573950773f);
        p = fmaf(p, w, -0.0076224613f);
        p = fmaf(p, w, 0.00943887047f);
        p = fmaf(p, w, 1.00167406f);
        p = fmaf(p, w, 2.83297682f);
    }
    return p * x;
}

__device__ __forceinline__ float bits_to_normal(uint32_t b) {
    float f = __uint_as_float((b >> 9) | 0x3f800000u) - 1.0f;
    const float minv = -0.99999994f;          /* nextafter(-1,0) */
    float u = fmaf(f, 2.0f, minv);            /* span rounds to exactly 2.0f */
    u = fmaxf(u, minv);
    return 1.41421356f * erfinv_xla(u);
}

/* PARTITIONABLE threefry (modern JAX default):
 * element i -> threefry2x32(key, hi32(i), lo32(i)); 32-bit draw = o0 ^ o1 */
__global__ void gen_normal_kernel(int which, const int* __restrict__ seed_ptr) {
    int n = which ? (D_N * EXTRA_N) : (D_N * POOL_N);
    int i = blockIdx.x * blockDim.x + threadIdx.x;
    if (i >= n) return;
    uint32_t k0 = 0u;
    uint32_t k1 = (uint32_t)(seed_ptr[0] + (which ? 9991 : 0));
    uint32_t o0, o1;
    threefry2x32(k0, k1, 0u, (uint32_t)i, o0, o1);
    float* out = which ? g_R : g_Apool;
    out[i] = bits_to_normal(o0 ^ o1);
}

/* ------------------------------------------------------------------ */
/* Centering                                                          */
/* ------------------------------------------------------------------ */
__global__ void colmean_kernel(const float* __restrict__ z) {
    int c = blockIdx.x * 128 + threadIdx.x;
    double s = 0.0;
    for (int b = 0; b < B_N; b++) s += (double)z[(size_t)b * D_N + c];
    g_means[c] = (float)(s * (1.0 / 2048.0));
}

__global__ void zc_kernel(const float* __restrict__ z) {
    int i = blockIdx.x * blockDim.x + threadIdx.x;
    g_zc[i] = z[i] - g_means[i & (D_N - 1)];
}

/* ------------------------------------------------------------------ */
/* Column normalize (f64 sum of squares)                              */
/* ------------------------------------------------------------------ */
__global__ void norm_cols_kernel(int which) {
    float* A = which ? g_R : g_Apool;
    int nc   = which ? EXTRA_N : POOL_N;
    int p = blockIdx.x * blockDim.x + threadIdx.x;
    if (p >= nc) return;
    double s = 0.0;
    for (int d = 0; d < D_N; d++) {
        float v = A[(size_t)d * nc + p];
        s += (double)v * (double)v;
    }
    float den = (float)sqrt(s) + 1e-12f;
    for (int d = 0; d < D_N; d++) A[(size_t)d * nc + p] /= den;
}

/* ------------------------------------------------------------------ */
/* fp32 GEMM: C^T[n*M+m] = sum_k zc[m,k] * Bmat[k,n]                  */
/* ------------------------------------------------------------------ */
__global__ void __launch_bounds__(256) gemm_kernel(int which) {
    const float* __restrict__ A  = g_zc;
    const float* __restrict__ Bm = which ? g_Afin : g_Apool;
    float*       __restrict__ Ct = which ? g_u2t  : g_ut;
    const int N = which ? AFIN_N : POOL_N;
    const int K = D_N, M = B_N;

    __shared__ float As[8][132];
    __shared__ float Bs[8][132];

    int tid = threadIdx.x;
    int tx = tid & 15, ty = tid >> 4;
    int m0 = blockIdx.y * 128, n0 = blockIdx.x * 128;

    int a_row = tid >> 1;
    int a_k4  = (tid & 1) * 4;
    int b_k   = tid >> 5;
    int b_n4  = (tid & 31) * 4;

    const float* Ap = A  + (size_t)(m0 + a_row) * K + a_k4;
    const float* Bp = Bm + (size_t)b_k * N + n0 + b_n4;

    float acc[8][8];
#pragma unroll
    for (int i = 0; i < 8; i++)
#pragma unroll
        for (int j = 0; j < 8; j++) acc[i][j] = 0.f;

    for (int k0 = 0; k0 < K; k0 += 8) {
        float4 av = *(const float4*)(Ap + k0);
        float4 bv = *(const float4*)(Bp + (size_t)k0 * N);
        __syncthreads();
        As[a_k4 + 0][a_row] = av.x;
        As[a_k4 + 1][a_row] = av.y;
        As[a_k4 + 2][a_row] = av.z;
        As[a_k4 + 3][a_row] = av.w;
        *(float4*)&Bs[b_k][b_n4] = bv;
        __syncthreads();
#pragma unroll
        for (int kk = 0; kk < 8; kk++) {
            float a[8], b[8];
#pragma unroll
            for (int i = 0; i < 8; i++) a[i] = As[kk][ty * 8 + i];
#pragma unroll
            for (int j = 0; j < 8; j++) b[j] = Bs[kk][tx * 8 + j];
#pragma unroll
            for (int i = 0; i < 8; i++)
#pragma unroll
                for (int j = 0; j < 8; j++)
                    acc[i][j] = fmaf(a[i], b[j], acc[i][j]);
        }
    }
#pragma unroll
    for (int j = 0; j < 8; j++) {
        int n = n0 + tx * 8 + j;
        float4 v0 = make_float4(acc[0][j], acc[1][j], acc[2][j], acc[3][j]);
        float4 v1 = make_float4(acc[4][j], acc[5][j], acc[6][j], acc[7][j]);
        *(float4*)&Ct[(size_t)n * M + m0 + ty * 8]     = v0;
        *(float4*)&Ct[(size_t)n * M + m0 + ty * 8 + 4] = v1;
    }
}

/* ------------------------------------------------------------------ */
/* ECF slice loss: fast __sincosf base + Chebyshev harmonics,         */
/* f64 block reduction.                                               */
/* ------------------------------------------------------------------ */
__global__ void __launch_bounds__(256) ecf_kernel(int which) {
    const float*  __restrict__ ut = which ? g_u2t : g_ut;
    double*       __restrict__ L  = which ? g_floss : g_losses;
    int a = blockIdx.x;
    int t = threadIdx.x;
    int lane = t & 31, warp = t >> 5;
    const float* row = ut + (size_t)a * B_N;

    float ar[8], ai[8];
#pragma unroll
    for (int j = 0; j < 8; j++) { ar[j] = 0.f; ai[j] = 0.f; }

    for (int b = t; b < B_N; b += 256) {
        float x = 0.625f * row[b];
        float s1, c1;
        __sincosf(x, &s1, &c1);
        float twoc = c1 + c1;
        float cm = 1.f, sm = 0.f;
        float c = c1, s = s1;
#pragma unroll
        for (int j = 0; j < 8; j++) {
            ar[j] += c; ai[j] += s;
            float cn = fmaf(twoc, c, -cm);
            float sn = fmaf(twoc, s, -sm);
            cm = c; sm = s; c = cn; s = sn;
        }
    }

    __shared__ double sred[8][16];
#pragma unroll
    for (int q = 0; q < 16; q++) {
        double v = (double)((q < 8) ? ar[q] : ai[q - 8]);
#pragma unroll
        for (int o = 16; o; o >>= 1) v += __shfl_xor_sync(0xffffffffu, v, o);
        if (lane == 0) sred[warp][q] = v;
    }
    __syncthreads();
    if (t < 16) {
        double tot = 0.0;
        for (int w = 0; w < 8; w++) tot += sred[w][t];
        sred[0][t] = tot;
    }
    __syncthreads();
    if (t == 0) {
        const double invB = 1.0 / 2048.0;
        double loss = 0.0;
#pragma unroll
        for (int j = 1; j <= 8; j++) {
            double tj = 0.625 * (double)j;
            double ph = exp(-0.5 * tj * tj);
            double re = sred[0][j - 1] * invB - ph;
            double im = sred[0][8 + j - 1] * invB;
            double integ = (re * re + im * im) * ph;
            loss += ((j == 8) ? 0.625 : 1.25) * integ;
        }
        L[a] = loss;
    }
}

/* ------------------------------------------------------------------ */
/* Bitonic sort of 2048 (loss f64): loss desc, idx asc                */
/* ------------------------------------------------------------------ */
__global__ void __launch_bounds__(1024) sort_kernel() {
    __shared__ double sv[2048];
    __shared__ int    si[2048];
    int t = threadIdx.x;
    for (int i = t; i < 2048; i += 1024) { sv[i] = g_losses[i]; si[i] = i; }
    __syncthreads();
    for (int k = 2; k <= 2048; k <<= 1) {
        for (int jj = k >> 1; jj > 0; jj >>= 1) {
            for (int i = t; i < 2048; i += 1024) {
                int ixj = i ^ jj;
                if (ixj > i) {
                    double va = sv[i], vb = sv[ixj];
                    int    ia = si[i], ib = si[ixj];
                    bool aFirst = (va > vb) || (va == vb && ia < ib);
                    bool dirAsc = ((i & k) == 0);
                    if (aFirst != dirAsc) {
                        sv[i] = vb; sv[ixj] = va;
                        si[i] = ib; si[ixj] = ia;
                    }
                }
            }
            __syncthreads();
        }
    }
    for (int i = t; i < HARD_N; i += 1024) g_ranked[i] = si[i];
}

/* ------------------------------------------------------------------ */
/* Classical Gram-Schmidt, single block of 256 threads                */
/* ------------------------------------------------------------------ */
__global__ void __launch_bounds__(256) gs_kernel() {
    __shared__ float sv[D_N];
    __shared__ float sc[HARD_N];
    __shared__ double red[8];
    int t = threadIdx.x;
    int lane = t & 31, warp = t >> 5;
    int d0 = t * 4;

    for (int j = 0; j < HARD_N; j++) {
        int col = g_ranked[j];
        float4 v;
        v.x = g_Apool[(size_t)(d0 + 0) * POOL_N + col];
        v.y = g_Apool[(size_t)(d0 + 1) * POOL_N + col];
        v.z = g_Apool[(size_t)(d0 + 2) * POOL_N + col];
        v.w = g_Apool[(size_t)(d0 + 3) * POOL_N + col];
        *(float4*)&sv[d0] = v;
        __syncthreads();

        for (int i = warp; i < j; i += 8) {
            const float4* qc  = (const float4*)(g_Q + (size_t)i * D_N);
            const float4* sv4 = (const float4*)sv;
            float part = 0.f;
            for (int dd = lane; dd < 256; dd += 32) {
                float4 q4 = qc[dd];
                float4 h4 = sv4[dd];
                part = fmaf(q4.x, h4.x, part);
                part = fmaf(q4.y, h4.y, part);
                part = fmaf(q4.z, h4.z, part);
                part = fmaf(q4.w, h4.w, part);
            }
#pragma unroll
            for (int o = 16; o; o >>= 1) part += __shfl_down_sync(0xffffffffu, part, o);
            if (lane == 0) sc[i] = part;
        }
        __syncthreads();

        float4 acc = make_float4(0.f, 0.f, 0.f, 0.f);
        for (int i = 0; i < j; i++) {
            float ci = sc[i];
            float4 q4 = *(const float4*)(g_Q + (size_t)i * D_N + d0);
            acc.x = fmaf(ci, q4.x, acc.x);
            acc.y = fmaf(ci, q4.y, acc.y);
            acc.z = fmaf(ci, q4.z, acc.z);
            acc.w = fmaf(ci, q4.w, acc.w);
        }
        v.x -= acc.x; v.y -= acc.y; v.z -= acc.z; v.w -= acc.w;

        double ss = (double)v.x * v.x + (double)v.y * v.y
                  + (double)v.z * v.z + (double)v.w * v.w;
#pragma unroll
        for (int o = 16; o; o >>= 1) ss += __shfl_down_sync(0xffffffffu, ss, o);
        if (lane == 0) red[warp] = ss;
        __syncthreads();
        if (t == 0) {
            double tot = 0.0;
            for (int w = 0; w < 8; w++) tot += red[w];
            red[0] = (double)fmaxf((float)sqrt(tot), 1e-12f);
        }
        __syncthreads();
        float nrm = (float)red[0];
        float4 o4 = make_float4(v.x / nrm, v.y / nrm, v.z / nrm, v.w / nrm);
        *(float4*)&g_Q[(size_t)j * D_N + d0] = o4;
        __syncthreads();
    }
}

/* ------------------------------------------------------------------ */
/* Extra directions: C = Q^T R ; R -= Q C                             */
/* ------------------------------------------------------------------ */
__global__ void qtr_kernel() {
    int i = blockIdx.x;
    int j = threadIdx.x;
    const float* q = g_Q + (size_t)i * D_N;
    float s = 0.f;
    for (int d = 0; d < D_N; d++)
        s = fmaf(q[d], g_R[(size_t)d * EXTRA_N + j], s);
    g_C[i * EXTRA_N + j] = s;
}

__global__ void subproj_kernel() {
    int idx = blockIdx.x * blockDim.x + threadIdx.x;
    int d = idx >> 6, j = idx & 63;
    float s = 0.f;
    for (int i = 0; i < HARD_N; i++)
        s = fmaf(g_Q[(size_t)i * D_N + d], g_C[i * EXTRA_N + j], s);
    g_R[idx] -= s;
}

__global__ void assemble_kernel() {
    int idx = blockIdx.x * blockDim.x + threadIdx.x;
    int d = idx >> 8, c = idx & 255;
    float v = 0.f;
    if (c < HARD_N)      v = g_Q[(size_t)c * D_N + d];
    else if (c < NFIN)   v = g_R[(size_t)d * EXTRA_N + (c - HARD_N)];
    g_Afin[idx] = v;
}

__global__ void final_kernel(float* __restrict__ out) {
    __shared__ double sh[256];
    int t = threadIdx.x;
    sh[t] = (t < NFIN) ? g_floss[t] : 0.0;
    __syncthreads();
    if (t == 0) {
        double s = 0.0;
        for (int i = 0; i < NFIN; i++) s += sh[i];
        out[0] = (float)((s / 192.0) * 2048.0);
    }
}

/* ------------------------------------------------------------------ */
extern "C" void kernel_launch(void* const* d_in, const int* in_sizes, int n_in,
                              void* d_out, int out_size) {
    const float* z; const int* seed;
    if (in_sizes[0] == 1) { seed = (const int*)d_in[0]; z = (const float*)d_in[1]; }
    else                  { z = (const float*)d_in[0]; seed = (const int*)d_in[1]; }
    float* out = (float*)d_out;

    colmean_kernel<<<8, 128>>>(z);
    zc_kernel<<<(B_N * D_N) / 256, 256>>>(z);

    gen_normal_kernel<<<(D_N * POOL_N) / 256, 256>>>(0, seed);
    norm_cols_kernel<<<16, 128>>>(0);

    gemm_kernel<<<dim3(POOL_N / 128, B_N / 128), 256>>>(0);
    ecf_kernel<<<POOL_N, 256>>>(0);

    sort_kernel<<<1, 1024>>>();
    gs_kernel<<<1, 256>>>();

    gen_normal_kernel<<<(D_N * EXTRA_N) / 256, 256>>>(1, seed);
    norm_cols_kernel<<<1, 64>>>(1);
    qtr_kernel<<<HARD_N, EXTRA_N>>>();
    subproj_kernel<<<(D_N * EXTRA_N) / 256, 256>>>();
    norm_cols_kernel<<<1, 64>>>(1);

    assemble_kernel<<<(D_N * AFIN_N) / 256, 256>>>();
    gemm_kernel<<<dim3(AFIN_N / 128, B_N / 128), 256>>>(1);
    ecf_kernel<<<NFIN, 256>>>(1);

    final_kernel<<<1, 256>>>(out);
}

// round 6
// speedup vs baseline: 1.6412x; 1.6412x over previous
#include <cuda_runtime.h>
#include <stdint.h>

#define B_N    2048
#define D_N    1024
#define POOL_N 2048
#define HARD_N 128
#define EXTRA_N 64
#define AFIN_N 256   /* padded; 192 real columns */
#define NFIN   192

/* ------------------------------------------------------------------ */
/* Scratch                                                            */
/* ------------------------------------------------------------------ */
__device__ float  g_Apool[D_N * POOL_N];
__device__ float  g_zc[B_N * D_N];
__device__ float  g_means[D_N];
__device__ float  g_ut[POOL_N * B_N];
__device__ float  g_u2t[AFIN_N * B_N];
__device__ double g_losses[POOL_N];
__device__ int    g_ranked[HARD_N];
__device__ float  g_Q[HARD_N * D_N];
__device__ float  g_R[D_N * EXTRA_N];
__device__ float  g_C[HARD_N * EXTRA_N];
__device__ float  g_Afin[D_N * AFIN_N];
__device__ double g_floss[NFIN];

/* compensated add: (hi,lo) += (bhi,blo), TwoSum, FMA-pipe only */
__device__ __forceinline__ void ff_add(float& hi, float& lo, float bhi, float blo) {
    float s  = hi + bhi;
    float bb = s - hi;
    float err = (hi - (s - bb)) + (bhi - bb);
    lo = lo + blo + err;
    hi = s;
}

/* ------------------------------------------------------------------ */
/* JAX threefry2x32 (20 rounds), partitionable mapping                */
/* ------------------------------------------------------------------ */
__device__ __forceinline__ uint32_t rotl32(uint32_t x, int r) {
    return (x << r) | (x >> (32 - r));
}

__device__ __forceinline__ void threefry2x32(uint32_t k0, uint32_t k1,
                                             uint32_t x0, uint32_t x1,
                                             uint32_t& o0, uint32_t& o1) {
    uint32_t ks2 = k0 ^ k1 ^ 0x1BD11BDAu;
    x0 += k0; x1 += k1;
#define TFR(r) { x0 += x1; x1 = rotl32(x1, (r)); x1 ^= x0; }
    TFR(13) TFR(15) TFR(26) TFR(6)  x0 += k1;  x1 += ks2 + 1u;
    TFR(17) TFR(29) TFR(16) TFR(24) x0 += ks2; x1 += k0  + 2u;
    TFR(13) TFR(15) TFR(26) TFR(6)  x0 += k0;  x1 += k1  + 3u;
    TFR(17) TFR(29) TFR(16) TFR(24) x0 += k1;  x1 += ks2 + 4u;
    TFR(13) TFR(15) TFR(26) TFR(6)  x0 += ks2; x1 += k0  + 5u;
#undef TFR
    o0 = x0; o1 = x1;
}

__device__ __forceinline__ float erfinv_xla(float x) {
    float w = -log1pf(-x * x);
    float p;
    if (w < 5.0f) {
        w -= 2.5f;
        p = 2.81022636e-08f;
        p = fmaf(p, w, 3.43273939e-07f);
        p = fmaf(p, w, -3.5233877e-06f);
        p = fmaf(p, w, -4.39150654e-06f);
        p = fmaf(p, w, 0.00021858087f);
        p = fmaf(p, w, -0.00125372503f);
        p = fmaf(p, w, -0.00417768164f);
        p = fmaf(p, w, 0.246640727f);
        p = fmaf(p, w, 1.50140941f);
    } else {
        w = sqrtf(w) - 3.0f;
        p = -0.000200214257f;
        p = fmaf(p, w, 0.000100950558f);
        p = fmaf(p, w, 0.00134934322f);
        p = fmaf(p, w, -0.00367342844f);
        p = fmaf(p, w, 0.00573950773f);
        p = fmaf(p, w, -0.0076224613f);
        p = fmaf(p, w, 0.00943887047f);
        p = fmaf(p, w, 1.00167406f);
        p = fmaf(p, w, 2.83297682f);
    }
    return p * x;
}

__device__ __forceinline__ float bits_to_normal(uint32_t b) {
    float f = __uint_as_float((b >> 9) | 0x3f800000u) - 1.0f;
    const float minv = -0.99999994f;
    float u = fmaf(f, 2.0f, minv);
    u = fmaxf(u, minv);
    return 1.41421356f * erfinv_xla(u);
}

__global__ void gen_normal_kernel(int which, const int* __restrict__ seed_ptr) {
    int n = which ? (D_N * EXTRA_N) : (D_N * POOL_N);
    int i = blockIdx.x * blockDim.x + threadIdx.x;
    if (i >= n) return;
    uint32_t k0 = 0u;
    uint32_t k1 = (uint32_t)(seed_ptr[0] + (which ? 9991 : 0));
    uint32_t o0, o1;
    threefry2x32(k0, k1, 0u, (uint32_t)i, o0, o1);
    float* out = which ? g_R : g_Apool;
    out[i] = bits_to_normal(o0 ^ o1);
}

/* ------------------------------------------------------------------ */
/* Column means: grid 8, block (128,8). Kahan per-thread, f64 scalar  */
/* finalize (16 DADD per column).                                     */
/* ------------------------------------------------------------------ */
__global__ void colmean_kernel(const float* __restrict__ z) {
    __shared__ float2 sm[8][128];
    int x = threadIdx.x, y = threadIdx.y;
    int c = blockIdx.x * 128 + x;
    float s = 0.f, comp = 0.f;
    for (int b = y; b < B_N; b += 8) {
        float v = z[(size_t)b * D_N + c];
        float yv = v - comp;
        float t = s + yv;
        comp = (t - s) - yv;
        s = t;
    }
    sm[y][x] = make_float2(s, comp);
    __syncthreads();
    if (y == 0) {
        double tot = 0.0;
        for (int w = 0; w < 8; w++) {
            float2 p = sm[w][x];
            tot += (double)p.x - (double)p.y;
        }
        g_means[c] = (float)(tot * (1.0 / 2048.0));
    }
}

__global__ void zc_kernel(const float* __restrict__ z) {
    int i = blockIdx.x * blockDim.x + threadIdx.x;
    g_zc[i] = z[i] - g_means[i & (D_N - 1)];
}

/* ------------------------------------------------------------------ */
/* Column normalize: grid nc/64, block (64,16). Kahan f32, f64 scalar */
/* finalize per column.                                               */
/* ------------------------------------------------------------------ */
__global__ void norm_cols_kernel(int which) {
    float* A = which ? g_R : g_Apool;
    int nc   = which ? EXTRA_N : POOL_N;
    __shared__ float2 sm[16][64];
    __shared__ float sden[64];
    int x = threadIdx.x, y = threadIdx.y;
    int col = blockIdx.x * 64 + x;

    float s = 0.f, comp = 0.f;
    for (int r = 0; r < 64; r++) {
        int d = y * 64 + r;
        float v = A[(size_t)d * nc + col];
        float v2 = v * v;
        float yv = v2 - comp;
        float t = s + yv;
        comp = (t - s) - yv;
        s = t;
    }
    sm[y][x] = make_float2(s, comp);
    __syncthreads();
    if (y == 0) {
        double tot = 0.0;
        for (int w = 0; w < 16; w++) {
            float2 p = sm[w][x];
            tot += (double)p.x - (double)p.y;
        }
        sden[x] = (float)sqrt(tot) + 1e-12f;
    }
    __syncthreads();
    float den = sden[x];
    for (int r = 0; r < 64; r++) {
        int d = y * 64 + r;
        A[(size_t)d * nc + col] /= den;
    }
}

/* ------------------------------------------------------------------ */
/* fp32 GEMM: C^T[n*M+m] = sum_k zc[m,k] * Bmat[k,n]                  */
/* ------------------------------------------------------------------ */
__global__ void __launch_bounds__(256) gemm_kernel(int which) {
    const float* __restrict__ A  = g_zc;
    const float* __restrict__ Bm = which ? g_Afin : g_Apool;
    float*       __restrict__ Ct = which ? g_u2t  : g_ut;
    const int N = which ? AFIN_N : POOL_N;
    const int K = D_N, M = B_N;

    __shared__ float As[8][132];
    __shared__ float Bs[8][132];

    int tid = threadIdx.x;
    int tx = tid & 15, ty = tid >> 4;
    int m0 = blockIdx.y * 128, n0 = blockIdx.x * 128;

    int a_row = tid >> 1;
    int a_k4  = (tid & 1) * 4;
    int b_k   = tid >> 5;
    int b_n4  = (tid & 31) * 4;

    const float* Ap = A  + (size_t)(m0 + a_row) * K + a_k4;
    const float* Bp = Bm + (size_t)b_k * N + n0 + b_n4;

    float acc[8][8];
#pragma unroll
    for (int i = 0; i < 8; i++)
#pragma unroll
        for (int j = 0; j < 8; j++) acc[i][j] = 0.f;

    for (int k0 = 0; k0 < K; k0 += 8) {
        float4 av = *(const float4*)(Ap + k0);
        float4 bv = *(const float4*)(Bp + (size_t)k0 * N);
        __syncthreads();
        As[a_k4 + 0][a_row] = av.x;
        As[a_k4 + 1][a_row] = av.y;
        As[a_k4 + 2][a_row] = av.z;
        As[a_k4 + 3][a_row] = av.w;
        *(float4*)&Bs[b_k][b_n4] = bv;
        __syncthreads();
#pragma unroll
        for (int kk = 0; kk < 8; kk++) {
            float a[8], b[8];
#pragma unroll
            for (int i = 0; i < 8; i++) a[i] = As[kk][ty * 8 + i];
#pragma unroll
            for (int j = 0; j < 8; j++) b[j] = Bs[kk][tx * 8 + j];
#pragma unroll
            for (int i = 0; i < 8; i++)
#pragma unroll
                for (int j = 0; j < 8; j++)
                    acc[i][j] = fmaf(a[i], b[j], acc[i][j]);
        }
    }
#pragma unroll
    for (int j = 0; j < 8; j++) {
        int n = n0 + tx * 8 + j;
        float4 v0 = make_float4(acc[0][j], acc[1][j], acc[2][j], acc[3][j]);
        float4 v1 = make_float4(acc[4][j], acc[5][j], acc[6][j], acc[7][j]);
        *(float4*)&Ct[(size_t)n * M + m0 + ty * 8]     = v0;
        *(float4*)&Ct[(size_t)n * M + m0 + ty * 8 + 4] = v1;
    }
}

/* ------------------------------------------------------------------ */
/* ECF slice loss: __sincosf + Chebyshev; compensated f32 reductions, */
/* f64 only for final per-block scalar loss math.                     */
/* ------------------------------------------------------------------ */
__global__ void __launch_bounds__(256) ecf_kernel(int which) {
    const float*  __restrict__ ut = which ? g_u2t : g_ut;
    double*       __restrict__ L  = which ? g_floss : g_losses;
    int a = blockIdx.x;
    int t = threadIdx.x;
    int lane = t & 31, warp = t >> 5;
    const float* row = ut + (size_t)a * B_N;

    float ar[8], ai[8];
#pragma unroll
    for (int j = 0; j < 8; j++) { ar[j] = 0.f; ai[j] = 0.f; }

    for (int b = t; b < B_N; b += 256) {
        float x = 0.625f * row[b];
        float s1, c1;
        __sincosf(x, &s1, &c1);
        float twoc = c1 + c1;
        float cm = 1.f, sm = 0.f;
        float c = c1, s = s1;
#pragma unroll
        for (int j = 0; j < 8; j++) {
            ar[j] += c; ai[j] += s;
            float cn = fmaf(twoc, c, -cm);
            float sn = fmaf(twoc, s, -sm);
            cm = c; sm = s; c = cn; s = sn;
        }
    }

    __shared__ float2 sred[8][16];
    __shared__ double sredd[16];
#pragma unroll
    for (int q = 0; q < 16; q++) {
        float hi = (q < 8) ? ar[q] : ai[q - 8];
        float lo = 0.f;
#pragma unroll
        for (int o = 16; o; o >>= 1) {
            float h2 = __shfl_xor_sync(0xffffffffu, hi, o);
            float l2 = __shfl_xor_sync(0xffffffffu, lo, o);
            ff_add(hi, lo, h2, l2);
        }
        if (lane == 0) sred[warp][q] = make_float2(hi, lo);
    }
    __syncthreads();
    if (t < 16) {
        double tot = 0.0;
        for (int w = 0; w < 8; w++) {
            float2 p = sred[w][t];
            tot += (double)p.x + (double)p.y;
        }
        sredd[t] = tot;
    }
    __syncthreads();
    if (t == 0) {
        const double invB = 1.0 / 2048.0;
        double loss = 0.0;
#pragma unroll
        for (int j = 1; j <= 8; j++) {
            double tj = 0.625 * (double)j;
            double ph = exp(-0.5 * tj * tj);
            double re = sredd[j - 1] * invB - ph;
            double im = sredd[8 + j - 1] * invB;
            double integ = (re * re + im * im) * ph;
            loss += ((j == 8) ? 0.625 : 1.25) * integ;
        }
        L[a] = loss;
    }
}

/* ------------------------------------------------------------------ */
/* Bitonic sort: int64 keys (positive doubles are bit-monotonic)      */
/* ------------------------------------------------------------------ */
__global__ void __launch_bounds__(1024) sort_kernel() {
    __shared__ long long sv[2048];
    __shared__ int       si[2048];
    int t = threadIdx.x;
    for (int i = t; i < 2048; i += 1024) {
        sv[i] = __double_as_longlong(g_losses[i]);
        si[i] = i;
    }
    __syncthreads();
    for (int k = 2; k <= 2048; k <<= 1) {
        for (int jj = k >> 1; jj > 0; jj >>= 1) {
            for (int i = t; i < 2048; i += 1024) {
                int ixj = i ^ jj;
                if (ixj > i) {
                    long long va = sv[i], vb = sv[ixj];
                    int       ia = si[i], ib = si[ixj];
                    bool aFirst = (va > vb) || (va == vb && ia < ib);
                    bool dirAsc = ((i & k) == 0);
                    if (aFirst != dirAsc) {
                        sv[i] = vb; sv[ixj] = va;
                        si[i] = ib; si[ixj] = ia;
                    }
                }
            }
            __syncthreads();
        }
    }
    for (int i = t; i < HARD_N; i += 1024) g_ranked[i] = si[i];
}

/* ------------------------------------------------------------------ */
/* Classical Gram-Schmidt, single block, all-f32                      */
/* ------------------------------------------------------------------ */
__global__ void __launch_bounds__(256) gs_kernel() {
    __shared__ float sv[D_N];
    __shared__ float sc[HARD_N];
    __shared__ float red[8];
    int t = threadIdx.x;
    int lane = t & 31, warp = t >> 5;
    int d0 = t * 4;

    for (int j = 0; j < HARD_N; j++) {
        int col = g_ranked[j];
        float4 v;
        v.x = g_Apool[(size_t)(d0 + 0) * POOL_N + col];
        v.y = g_Apool[(size_t)(d0 + 1) * POOL_N + col];
        v.z = g_Apool[(size_t)(d0 + 2) * POOL_N + col];
        v.w = g_Apool[(size_t)(d0 + 3) * POOL_N + col];
        *(float4*)&sv[d0] = v;
        __syncthreads();

        for (int i = warp; i < j; i += 8) {
            const float4* qc  = (const float4*)(g_Q + (size_t)i * D_N);
            const float4* sv4 = (const float4*)sv;
            float part = 0.f;
            for (int dd = lane; dd < 256; dd += 32) {
                float4 q4 = qc[dd];
                float4 h4 = sv4[dd];
                part = fmaf(q4.x, h4.x, part);
                part = fmaf(q4.y, h4.y, part);
                part = fmaf(q4.z, h4.z, part);
                part = fmaf(q4.w, h4.w, part);
            }
#pragma unroll
            for (int o = 16; o; o >>= 1) part += __shfl_down_sync(0xffffffffu, part, o);
            if (lane == 0) sc[i] = part;
        }
        __syncthreads();

        float4 acc = make_float4(0.f, 0.f, 0.f, 0.f);
        for (int i = 0; i < j; i++) {
            float ci = sc[i];
            float4 q4 = *(const float4*)(g_Q + (size_t)i * D_N + d0);
            acc.x = fmaf(ci, q4.x, acc.x);
            acc.y = fmaf(ci, q4.y, acc.y);
            acc.z = fmaf(ci, q4.z, acc.z);
            acc.w = fmaf(ci, q4.w, acc.w);
        }
        v.x -= acc.x; v.y -= acc.y; v.z -= acc.z; v.w -= acc.w;

        float ss = fmaf(v.x, v.x, fmaf(v.y, v.y, fmaf(v.z, v.z, v.w * v.w)));
#pragma unroll
        for (int o = 16; o; o >>= 1) ss += __shfl_down_sync(0xffffffffu, ss, o);
        if (lane == 0) red[warp] = ss;
        __syncthreads();
        if (t == 0) {
            float tot = 0.f;
            for (int w = 0; w < 8; w++) tot += red[w];
            red[0] = fmaxf(sqrtf(tot), 1e-12f);
        }
        __syncthreads();
        float nrm = red[0];
        float4 o4 = make_float4(v.x / nrm, v.y / nrm, v.z / nrm, v.w / nrm);
        *(float4*)&g_Q[(size_t)j * D_N + d0] = o4;
        __syncthreads();
    }
}

/* ------------------------------------------------------------------ */
/* Extra directions                                                   */
/* ------------------------------------------------------------------ */
__global__ void qtr_kernel() {
    int i = blockIdx.x;
    int j = threadIdx.x;
    const float* q = g_Q + (size_t)i * D_N;
    float s = 0.f;
    for (int d = 0; d < D_N; d++)
        s = fmaf(q[d], g_R[(size_t)d * EXTRA_N + j], s);
    g_C[i * EXTRA_N + j] = s;
}

__global__ void subproj_kernel() {
    int idx = blockIdx.x * blockDim.x + threadIdx.x;
    int d = idx >> 6, j = idx & 63;
    float s = 0.f;
    for (int i = 0; i < HARD_N; i++)
        s = fmaf(g_Q[(size_t)i * D_N + d], g_C[i * EXTRA_N + j], s);
    g_R[idx] -= s;
}

__global__ void assemble_kernel() {
    int idx = blockIdx.x * blockDim.x + threadIdx.x;
    int d = idx >> 8, c = idx & 255;
    float v = 0.f;
    if (c < HARD_N)      v = g_Q[(size_t)c * D_N + d];
    else if (c < NFIN)   v = g_R[(size_t)d * EXTRA_N + (c - HARD_N)];
    g_Afin[idx] = v;
}

__global__ void final_kernel(float* __restrict__ out) {
    __shared__ double sh[256];
    int t = threadIdx.x;
    sh[t] = (t < NFIN) ? g_floss[t] : 0.0;
    __syncthreads();
    if (t == 0) {
        double s = 0.0;
        for (int i = 0; i < NFIN; i++) s += sh[i];
        out[0] = (float)((s / 192.0) * 2048.0);
    }
}

/* ------------------------------------------------------------------ */
extern "C" void kernel_launch(void* const* d_in, const int* in_sizes, int n_in,
                              void* d_out, int out_size) {
    const float* z; const int* seed;
    if (in_sizes[0] == 1) { seed = (const int*)d_in[0]; z = (const float*)d_in[1]; }
    else                  { z = (const float*)d_in[0]; seed = (const int*)d_in[1]; }
    float* out = (float*)d_out;

    colmean_kernel<<<8, dim3(128, 8)>>>(z);
    zc_kernel<<<(B_N * D_N) / 256, 256>>>(z);

    gen_normal_kernel<<<(D_N * POOL_N) / 256, 256>>>(0, seed);
    norm_cols_kernel<<<POOL_N / 64, dim3(64, 16)>>>(0);

    gemm_kernel<<<dim3(POOL_N / 128, B_N / 128), 256>>>(0);
    ecf_kernel<<<POOL_N, 256>>>(0);

    sort_kernel<<<1, 1024>>>();
    gs_kernel<<<1, 256>>>();

    gen_normal_kernel<<<(D_N * EXTRA_N) / 256, 256>>>(1, seed);
    norm_cols_kernel<<<1, dim3(64, 16)>>>(1);
    qtr_kernel<<<HARD_N, EXTRA_N>>>();
    subproj_kernel<<<(D_N * EXTRA_N) / 256, 256>>>();
    norm_cols_kernel<<<1, dim3(64, 16)>>>(1);

    assemble_kernel<<<(D_N * AFIN_N) / 256, 256>>>();
    gemm_kernel<<<dim3(AFIN_N / 128, B_N / 128), 256>>>(1);
    ecf_kernel<<<NFIN, 256>>>(1);

    final_kernel<<<1, 256>>>(out);
}

// round 7
// speedup vs baseline: 3.7533x; 2.2869x over previous
#include <cuda_runtime.h>
#include <stdint.h>

#define B_N    2048
#define D_N    1024
#define POOL_N 2048
#define HARD_N 128
#define EXTRA_N 64
#define AFIN_N 256   /* padded; 192 real columns */
#define NFIN   192

/* ------------------------------------------------------------------ */
/* Scratch                                                            */
/* ------------------------------------------------------------------ */
__device__ float  g_Apool[D_N * POOL_N];
__device__ float  g_zc[B_N * D_N];
__device__ float  g_means[D_N];
__device__ float  g_ut[POOL_N * B_N];
__device__ float  g_u2t[AFIN_N * B_N];
__device__ double g_losses[POOL_N];
__device__ int    g_ranked[HARD_N];
__device__ float  g_H[HARD_N * D_N];      /* H^T: [i][d] */
__device__ float  g_G[HARD_N * HARD_N];   /* Gram matrix */
__device__ float  g_T[HARD_N * HARD_N];   /* R^{-1}, row-major [k][j] */
__device__ float  g_Q[HARD_N * D_N];      /* q_i at i*1024 */
__device__ float  g_R[D_N * EXTRA_N];
__device__ float  g_C[HARD_N * EXTRA_N];
__device__ float  g_Afin[D_N * AFIN_N];
__device__ double g_floss[NFIN];

/* compensated add: (hi,lo) += (bhi,blo) */
__device__ __forceinline__ void ff_add(float& hi, float& lo, float bhi, float blo) {
    float s  = hi + bhi;
    float bb = s - hi;
    float err = (hi - (s - bb)) + (bhi - bb);
    lo = lo + blo + err;
    hi = s;
}

/* ------------------------------------------------------------------ */
/* JAX threefry2x32 (20 rounds), partitionable mapping                */
/* ------------------------------------------------------------------ */
__device__ __forceinline__ uint32_t rotl32(uint32_t x, int r) {
    return (x << r) | (x >> (32 - r));
}

__device__ __forceinline__ void threefry2x32(uint32_t k0, uint32_t k1,
                                             uint32_t x0, uint32_t x1,
                                             uint32_t& o0, uint32_t& o1) {
    uint32_t ks2 = k0 ^ k1 ^ 0x1BD11BDAu;
    x0 += k0; x1 += k1;
#define TFR(r) { x0 += x1; x1 = rotl32(x1, (r)); x1 ^= x0; }
    TFR(13) TFR(15) TFR(26) TFR(6)  x0 += k1;  x1 += ks2 + 1u;
    TFR(17) TFR(29) TFR(16) TFR(24) x0 += ks2; x1 += k0  + 2u;
    TFR(13) TFR(15) TFR(26) TFR(6)  x0 += k0;  x1 += k1  + 3u;
    TFR(17) TFR(29) TFR(16) TFR(24) x0 += k1;  x1 += ks2 + 4u;
    TFR(13) TFR(15) TFR(26) TFR(6)  x0 += ks2; x1 += k0  + 5u;
#undef TFR
    o0 = x0; o1 = x1;
}

__device__ __forceinline__ float erfinv_xla(float x) {
    float w = -log1pf(-x * x);
    float p;
    if (w < 5.0f) {
        w -= 2.5f;
        p = 2.81022636e-08f;
        p = fmaf(p, w, 3.43273939e-07f);
        p = fmaf(p, w, -3.5233877e-06f);
        p = fmaf(p, w, -4.39150654e-06f);
        p = fmaf(p, w, 0.00021858087f);
        p = fmaf(p, w, -0.00125372503f);
        p = fmaf(p, w, -0.00417768164f);
        p = fmaf(p, w, 0.246640727f);
        p = fmaf(p, w, 1.50140941f);
    } else {
        w = sqrtf(w) - 3.0f;
        p = -0.000200214257f;
        p = fmaf(p, w, 0.000100950558f);
        p = fmaf(p, w, 0.00134934322f);
        p = fmaf(p, w, -0.00367342844f);
        p = fmaf(p, w, 0.00573950773f);
        p = fmaf(p, w, -0.0076224613f);
        p = fmaf(p, w, 0.00943887047f);
        p = fmaf(p, w, 1.00167406f);
        p = fmaf(p, w, 2.83297682f);
    }
    return p * x;
}

__device__ __forceinline__ float bits_to_normal(uint32_t b) {
    float f = __uint_as_float((b >> 9) | 0x3f800000u) - 1.0f;
    const float minv = -0.99999994f;
    float u = fmaf(f, 2.0f, minv);
    u = fmaxf(u, minv);
    return 1.41421356f * erfinv_xla(u);
}

__global__ void gen_normal_kernel(int which, const int* __restrict__ seed_ptr) {
    int n = which ? (D_N * EXTRA_N) : (D_N * POOL_N);
    int i = blockIdx.x * blockDim.x + threadIdx.x;
    if (i >= n) return;
    uint32_t k0 = 0u;
    uint32_t k1 = (uint32_t)(seed_ptr[0] + (which ? 9991 : 0));
    uint32_t o0, o1;
    threefry2x32(k0, k1, 0u, (uint32_t)i, o0, o1);
    float* out = which ? g_R : g_Apool;
    out[i] = bits_to_normal(o0 ^ o1);
}

/* ------------------------------------------------------------------ */
/* Column means                                                       */
/* ------------------------------------------------------------------ */
__global__ void colmean_kernel(const float* __restrict__ z) {
    __shared__ float2 sm[8][128];
    int x = threadIdx.x, y = threadIdx.y;
    int c = blockIdx.x * 128 + x;
    float s = 0.f, comp = 0.f;
    for (int b = y; b < B_N; b += 8) {
        float v = z[(size_t)b * D_N + c];
        float yv = v - comp;
        float t = s + yv;
        comp = (t - s) - yv;
        s = t;
    }
    sm[y][x] = make_float2(s, comp);
    __syncthreads();
    if (y == 0) {
        double tot = 0.0;
        for (int w = 0; w < 8; w++) {
            float2 p = sm[w][x];
            tot += (double)p.x - (double)p.y;
        }
        g_means[c] = (float)(tot * (1.0 / 2048.0));
    }
}

__global__ void zc_kernel(const float* __restrict__ z) {
    int i = blockIdx.x * blockDim.x + threadIdx.x;
    g_zc[i] = z[i] - g_means[i & (D_N - 1)];
}

/* ------------------------------------------------------------------ */
/* Column normalize                                                   */
/* ------------------------------------------------------------------ */
__global__ void norm_cols_kernel(int which) {
    float* A = which ? g_R : g_Apool;
    int nc   = which ? EXTRA_N : POOL_N;
    __shared__ float2 sm[16][64];
    __shared__ float sden[64];
    int x = threadIdx.x, y = threadIdx.y;
    int col = blockIdx.x * 64 + x;

    float s = 0.f, comp = 0.f;
    for (int r = 0; r < 64; r++) {
        int d = y * 64 + r;
        float v = A[(size_t)d * nc + col];
        float v2 = v * v;
        float yv = v2 - comp;
        float t = s + yv;
        comp = (t - s) - yv;
        s = t;
    }
    sm[y][x] = make_float2(s, comp);
    __syncthreads();
    if (y == 0) {
        double tot = 0.0;
        for (int w = 0; w < 16; w++) {
            float2 p = sm[w][x];
            tot += (double)p.x - (double)p.y;
        }
        sden[x] = (float)sqrt(tot) + 1e-12f;
    }
    __syncthreads();
    float den = sden[x];
    for (int r = 0; r < 64; r++) {
        int d = y * 64 + r;
        A[(size_t)d * nc + col] /= den;
    }
}

/* ------------------------------------------------------------------ */
/* fp32 GEMM: C^T[n*M+m] = sum_k zc[m,k] * Bmat[k,n]                  */
/* ------------------------------------------------------------------ */
__global__ void __launch_bounds__(256) gemm_kernel(int which) {
    const float* __restrict__ A  = g_zc;
    const float* __restrict__ Bm = which ? g_Afin : g_Apool;
    float*       __restrict__ Ct = which ? g_u2t  : g_ut;
    const int N = which ? AFIN_N : POOL_N;
    const int K = D_N, M = B_N;

    __shared__ float As[8][132];
    __shared__ float Bs[8][132];

    int tid = threadIdx.x;
    int tx = tid & 15, ty = tid >> 4;
    int m0 = blockIdx.y * 128, n0 = blockIdx.x * 128;

    int a_row = tid >> 1;
    int a_k4  = (tid & 1) * 4;
    int b_k   = tid >> 5;
    int b_n4  = (tid & 31) * 4;

    const float* Ap = A  + (size_t)(m0 + a_row) * K + a_k4;
    const float* Bp = Bm + (size_t)b_k * N + n0 + b_n4;

    float acc[8][8];
#pragma unroll
    for (int i = 0; i < 8; i++)
#pragma unroll
        for (int j = 0; j < 8; j++) acc[i][j] = 0.f;

    for (int k0 = 0; k0 < K; k0 += 8) {
        float4 av = *(const float4*)(Ap + k0);
        float4 bv = *(const float4*)(Bp + (size_t)k0 * N);
        __syncthreads();
        As[a_k4 + 0][a_row] = av.x;
        As[a_k4 + 1][a_row] = av.y;
        As[a_k4 + 2][a_row] = av.z;
        As[a_k4 + 3][a_row] = av.w;
        *(float4*)&Bs[b_k][b_n4] = bv;
        __syncthreads();
#pragma unroll
        for (int kk = 0; kk < 8; kk++) {
            float a[8], b[8];
#pragma unroll
            for (int i = 0; i < 8; i++) a[i] = As[kk][ty * 8 + i];
#pragma unroll
            for (int j = 0; j < 8; j++) b[j] = Bs[kk][tx * 8 + j];
#pragma unroll
            for (int i = 0; i < 8; i++)
#pragma unroll
                for (int j = 0; j < 8; j++)
                    acc[i][j] = fmaf(a[i], b[j], acc[i][j]);
        }
    }
#pragma unroll
    for (int j = 0; j < 8; j++) {
        int n = n0 + tx * 8 + j;
        float4 v0 = make_float4(acc[0][j], acc[1][j], acc[2][j], acc[3][j]);
        float4 v1 = make_float4(acc[4][j], acc[5][j], acc[6][j], acc[7][j]);
        *(float4*)&Ct[(size_t)n * M + m0 + ty * 8]     = v0;
        *(float4*)&Ct[(size_t)n * M + m0 + ty * 8 + 4] = v1;
    }
}

/* ------------------------------------------------------------------ */
/* ECF slice loss: float4 loads, __sincosf + Chebyshev,               */
/* compensated f32 reductions, f64 scalar finalize.                   */
/* ------------------------------------------------------------------ */
__device__ __forceinline__ void ecf_sample(float x, float ar[8], float ai[8]) {
    float s1, c1;
    __sincosf(x, &s1, &c1);
    float twoc = c1 + c1;
    float cm = 1.f, sm = 0.f;
    float c = c1, s = s1;
#pragma unroll
    for (int j = 0; j < 8; j++) {
        ar[j] += c; ai[j] += s;
        float cn = fmaf(twoc, c, -cm);
        float sn = fmaf(twoc, s, -sm);
        cm = c; sm = s; c = cn; s = sn;
    }
}

__global__ void __launch_bounds__(256) ecf_kernel(int which) {
    const float*  __restrict__ ut = which ? g_u2t : g_ut;
    double*       __restrict__ L  = which ? g_floss : g_losses;
    int a = blockIdx.x;
    int t = threadIdx.x;
    int lane = t & 31, warp = t >> 5;
    const float4* row4 = (const float4*)(ut + (size_t)a * B_N);

    float ar[8], ai[8];
#pragma unroll
    for (int j = 0; j < 8; j++) { ar[j] = 0.f; ai[j] = 0.f; }

#pragma unroll
    for (int it = 0; it < 2; it++) {
        float4 xv = row4[t + 256 * it];
        ecf_sample(0.625f * xv.x, ar, ai);
        ecf_sample(0.625f * xv.y, ar, ai);
        ecf_sample(0.625f * xv.z, ar, ai);
        ecf_sample(0.625f * xv.w, ar, ai);
    }

    __shared__ float2 sred[8][16];
    __shared__ double sredd[16];
#pragma unroll
    for (int q = 0; q < 16; q++) {
        float hi = (q < 8) ? ar[q] : ai[q - 8];
        float lo = 0.f;
#pragma unroll
        for (int o = 16; o; o >>= 1) {
            float h2 = __shfl_xor_sync(0xffffffffu, hi, o);
            float l2 = __shfl_xor_sync(0xffffffffu, lo, o);
            ff_add(hi, lo, h2, l2);
        }
        if (lane == 0) sred[warp][q] = make_float2(hi, lo);
    }
    __syncthreads();
    if (t < 16) {
        double tot = 0.0;
        for (int w = 0; w < 8; w++) {
            float2 p = sred[w][t];
            tot += (double)p.x + (double)p.y;
        }
        sredd[t] = tot;
    }
    __syncthreads();
    if (t == 0) {
        const double invB = 1.0 / 2048.0;
        double loss = 0.0;
#pragma unroll
        for (int j = 1; j <= 8; j++) {
            double tj = 0.625 * (double)j;
            double ph = exp(-0.5 * tj * tj);
            double re = sredd[j - 1] * invB - ph;
            double im = sredd[8 + j - 1] * invB;
            double integ = (re * re + im * im) * ph;
            loss += ((j == 8) ? 0.625 : 1.25) * integ;
        }
        L[a] = loss;
    }
}

/* ------------------------------------------------------------------ */
/* Bitonic sort: int64 keys                                           */
/* ------------------------------------------------------------------ */
__global__ void __launch_bounds__(1024) sort_kernel() {
    __shared__ long long sv[2048];
    __shared__ int       si[2048];
    int t = threadIdx.x;
    for (int i = t; i < 2048; i += 1024) {
        sv[i] = __double_as_longlong(g_losses[i]);
        si[i] = i;
    }
    __syncthreads();
    for (int k = 2; k <= 2048; k <<= 1) {
        for (int jj = k >> 1; jj > 0; jj >>= 1) {
            for (int i = t; i < 2048; i += 1024) {
                int ixj = i ^ jj;
                if (ixj > i) {
                    long long va = sv[i], vb = sv[ixj];
                    int       ia = si[i], ib = si[ixj];
                    bool aFirst = (va > vb) || (va == vb && ia < ib);
                    bool dirAsc = ((i & k) == 0);
                    if (aFirst != dirAsc) {
                        sv[i] = vb; sv[ixj] = va;
                        si[i] = ib; si[ixj] = ia;
                    }
                }
            }
            __syncthreads();
        }
    }
    for (int i = t; i < HARD_N; i += 1024) g_ranked[i] = si[i];
}

/* ------------------------------------------------------------------ */
/* GS via Cholesky: gather H, G=H^T H, R=chol(G), T=R^{-1}, Q=H T     */
/* ------------------------------------------------------------------ */
__global__ void gather_kernel() {
    int idx = blockIdx.x * 256 + threadIdx.x;   /* 131072 */
    int i = idx >> 10, d = idx & 1023;
    g_H[idx] = g_Apool[(size_t)d * POOL_N + g_ranked[i]];
}

__global__ void __launch_bounds__(256) syrk_kernel() {
    int i = blockIdx.x;                 /* row of G */
    __shared__ float hi[D_N];
    int tid = threadIdx.x;
    *(float4*)&hi[tid * 4] = *(const float4*)&g_H[(size_t)i * D_N + tid * 4];
    __syncthreads();
    int lane = tid & 31, warp = tid >> 5;
    const float4* hi4 = (const float4*)hi;
    for (int j = warp; j < HARD_N; j += 8) {
        const float4* hj = (const float4*)&g_H[(size_t)j * D_N];
        float acc = 0.f;
        for (int d4 = lane; d4 < 256; d4 += 32) {
            float4 a = hi4[d4];
            float4 b = hj[d4];
            acc = fmaf(a.x, b.x, fmaf(a.y, b.y, fmaf(a.z, b.z, fmaf(a.w, b.w, acc))));
        }
#pragma unroll
        for (int o = 16; o; o >>= 1) acc += __shfl_down_sync(0xffffffffu, acc, o);
        if (lane == 0) g_G[i * HARD_N + j] = acc;
    }
}

/* single block, 128 threads; dynamic smem: sR[16384] + sT[16384] */
__global__ void __launch_bounds__(128) cholinv_kernel() {
    extern __shared__ float sbuf[];
    float* sR = sbuf;
    float* sT = sbuf + HARD_N * HARD_N;
    int m = threadIdx.x;
    __shared__ float sdiag;

    for (int k = 0; k < HARD_N; k++) {
        sR[k * HARD_N + m] = g_G[k * HARD_N + m];
        sT[k * HARD_N + m] = 0.f;
    }
    __syncthreads();

    /* Cholesky: R upper-triangular, G = R^T R. Row j computed at step j. */
    for (int j = 0; j < HARD_N; j++) {
        float s0 = 0.f, s1 = 0.f;
        int k = 0;
        for (; k + 2 <= j; k += 2) {
            s0 = fmaf(sR[k * HARD_N + j],       sR[k * HARD_N + m],       s0);
            s1 = fmaf(sR[(k + 1) * HARD_N + j], sR[(k + 1) * HARD_N + m], s1);
        }
        if (k < j) s0 = fmaf(sR[k * HARD_N + j], sR[k * HARD_N + m], s0);
        float smm = s0 + s1;
        if (m == j) {
            float dd = sR[j * HARD_N + j] - smm;
            float r  = sqrtf(fmaxf(dd, 0.f));
            sdiag = fmaxf(r, 1e-12f);
        }
        __syncthreads();
        float rjj = sdiag;
        if (m > j)       sR[j * HARD_N + m] = (sR[j * HARD_N + m] - smm) / rjj;
        else if (m == j) sR[j * HARD_N + j] = rjj;
        __syncthreads();
    }

    /* T = R^{-1}: thread m owns column m. */
    int jc = m;
    sT[jc * HARD_N + jc] = 1.f / sR[jc * HARD_N + jc];
    for (int i = HARD_N - 2; i >= 0; i--) {
        float a0 = 0.f, a1 = 0.f;
        int k = i + 1;
        for (; k + 2 <= HARD_N; k += 2) {
            a0 = fmaf(sR[i * HARD_N + k],       sT[k * HARD_N + jc],       a0);
            a1 = fmaf(sR[i * HARD_N + k + 1],   sT[(k + 1) * HARD_N + jc], a1);
        }
        if (k < HARD_N) a0 = fmaf(sR[i * HARD_N + k], sT[k * HARD_N + jc], a0);
        if (i < jc) sT[i * HARD_N + jc] = -(a0 + a1) / sR[i * HARD_N + i];
    }
    __syncthreads();
    for (int k = 0; k < HARD_N; k++)
        g_T[k * HARD_N + m] = sT[k * HARD_N + m];
}

/* Q = H * T : g_Q[j*1024+d] = sum_k H[k][d] * T[k][j] */
__global__ void __launch_bounds__(256) qht_kernel() {
    int j = threadIdx.x & 127;
    int d = blockIdx.x * 2 + (threadIdx.x >> 7);
    float a0 = 0.f, a1 = 0.f;
    for (int k = 0; k < HARD_N; k += 2) {
        float h0 = g_H[(size_t)k * D_N + d];
        float h1 = g_H[(size_t)(k + 1) * D_N + d];
        a0 = fmaf(h0, g_T[k * HARD_N + j], a0);
        a1 = fmaf(h1, g_T[(k + 1) * HARD_N + j], a1);
    }
    g_Q[(size_t)j * D_N + d] = a0 + a1;
}

/* ------------------------------------------------------------------ */
/* Extra directions                                                   */
/* ------------------------------------------------------------------ */
__global__ void qtr_kernel() {
    int i = blockIdx.x;
    int j = threadIdx.x;
    const float* q = g_Q + (size_t)i * D_N;
    float s = 0.f;
    for (int d = 0; d < D_N; d++)
        s = fmaf(q[d], g_R[(size_t)d * EXTRA_N + j], s);
    g_C[i * EXTRA_N + j] = s;
}

__global__ void subproj_kernel() {
    int idx = blockIdx.x * blockDim.x + threadIdx.x;
    int d = idx >> 6, j = idx & 63;
    float s = 0.f;
    for (int i = 0; i < HARD_N; i++)
        s = fmaf(g_Q[(size_t)i * D_N + d], g_C[i * EXTRA_N + j], s);
    g_R[idx] -= s;
}

__global__ void assemble_kernel() {
    int idx = blockIdx.x * blockDim.x + threadIdx.x;
    int d = idx >> 8, c = idx & 255;
    float v = 0.f;
    if (c < HARD_N)      v = g_Q[(size_t)c * D_N + d];
    else if (c < NFIN)   v = g_R[(size_t)d * EXTRA_N + (c - HARD_N)];
    g_Afin[idx] = v;
}

__global__ void final_kernel(float* __restrict__ out) {
    __shared__ double sh[256];
    int t = threadIdx.x;
    sh[t] = (t < NFIN) ? g_floss[t] : 0.0;
    __syncthreads();
    if (t == 0) {
        double s = 0.0;
        for (int i = 0; i < NFIN; i++) s += sh[i];
        out[0] = (float)((s / 192.0) * 2048.0);
    }
}

/* ------------------------------------------------------------------ */
extern "C" void kernel_launch(void* const* d_in, const int* in_sizes, int n_in,
                              void* d_out, int out_size) {
    const float* z; const int* seed;
    if (in_sizes[0] == 1) { seed = (const int*)d_in[0]; z = (const float*)d_in[1]; }
    else                  { z = (const float*)d_in[0]; seed = (const int*)d_in[1]; }
    float* out = (float*)d_out;

    static int smem_set = 0;
    if (!smem_set) {
        cudaFuncSetAttribute(cholinv_kernel,
                             cudaFuncAttributeMaxDynamicSharedMemorySize,
                             2 * HARD_N * HARD_N * (int)sizeof(float));
        smem_set = 1;
    }

    colmean_kernel<<<8, dim3(128, 8)>>>(z);
    zc_kernel<<<(B_N * D_N) / 256, 256>>>(z);

    gen_normal_kernel<<<(D_N * POOL_N) / 256, 256>>>(0, seed);
    norm_cols_kernel<<<POOL_N / 64, dim3(64, 16)>>>(0);

    gemm_kernel<<<dim3(POOL_N / 128, B_N / 128), 256>>>(0);
    ecf_kernel<<<POOL_N, 256>>>(0);

    sort_kernel<<<1, 1024>>>();

    gather_kernel<<<(HARD_N * D_N) / 256, 256>>>();
    syrk_kernel<<<HARD_N, 256>>>();
    cholinv_kernel<<<1, 128, 2 * HARD_N * HARD_N * sizeof(float)>>>();
    qht_kernel<<<D_N / 2, 256>>>();

    gen_normal_kernel<<<(D_N * EXTRA_N) / 256, 256>>>(1, seed);
    norm_cols_kernel<<<1, dim3(64, 16)>>>(1);
    qtr_kernel<<<HARD_N, EXTRA_N>>>();
    subproj_kernel<<<(D_N * EXTRA_N) / 256, 256>>>();
    norm_cols_kernel<<<1, dim3(64, 16)>>>(1);

    assemble_kernel<<<(D_N * AFIN_N) / 256, 256>>>();
    gemm_kernel<<<dim3(AFIN_N / 128, B_N / 128), 256>>>(1);
    ecf_kernel<<<NFIN, 256>>>(1);

    final_kernel<<<1, 256>>>(out);
}

// round 8
// speedup vs baseline: 4.0545x; 1.0803x over previous
#include <cuda_runtime.h>
#include <stdint.h>

#define B_N    2048
#define D_N    1024
#define POOL_N 2048
#define HARD_N 128
#define EXTRA_N 64
#define AFIN_N 256   /* padded; 192 real columns */
#define NFIN   192

#define BM 256
#define BN 128

/* ------------------------------------------------------------------ */
/* Scratch                                                            */
/* ------------------------------------------------------------------ */
__device__ float  g_Apool[D_N * POOL_N];
__device__ float  g_means[D_N];
__device__ float  g_ut[POOL_N * B_N];
__device__ float  g_u2t[AFIN_N * B_N];
__device__ double g_losses[POOL_N];
__device__ int    g_ranked[HARD_N];
__device__ float  g_H[HARD_N * D_N];
__device__ float  g_G[HARD_N * HARD_N];
__device__ float  g_T[HARD_N * HARD_N];
__device__ float  g_Q[HARD_N * D_N];
__device__ float  g_R[D_N * EXTRA_N];
__device__ float  g_C[HARD_N * EXTRA_N];
__device__ float  g_Afin[D_N * AFIN_N];
__device__ double g_floss[NFIN];

/* ---------------- packed f32x2 helpers ---------------------------- */
__device__ __forceinline__ unsigned long long bcast2(float x) {
    unsigned long long r;
    asm("mov.b64 %0, {%1, %1};" : "=l"(r) : "f"(x));
    return r;
}
__device__ __forceinline__ void fma2(unsigned long long& d,
                                     unsigned long long a,
                                     unsigned long long b) {
    asm("fma.rn.f32x2 %0, %1, %2, %0;" : "+l"(d) : "l"(a), "l"(b));
}
__device__ __forceinline__ float2 unpk2(unsigned long long v) {
    float2 r;
    asm("mov.b64 {%0, %1}, %2;" : "=f"(r.x), "=f"(r.y) : "l"(v));
    return r;
}

/* compensated add */
__device__ __forceinline__ void ff_add(float& hi, float& lo, float bhi, float blo) {
    float s  = hi + bhi;
    float bb = s - hi;
    float err = (hi - (s - bb)) + (bhi - bb);
    lo = lo + blo + err;
    hi = s;
}

/* ------------------------------------------------------------------ */
/* JAX threefry2x32 (partitionable)                                   */
/* ------------------------------------------------------------------ */
__device__ __forceinline__ uint32_t rotl32(uint32_t x, int r) {
    return (x << r) | (x >> (32 - r));
}

__device__ __forceinline__ void threefry2x32(uint32_t k0, uint32_t k1,
                                             uint32_t x0, uint32_t x1,
                                             uint32_t& o0, uint32_t& o1) {
    uint32_t ks2 = k0 ^ k1 ^ 0x1BD11BDAu;
    x0 += k0; x1 += k1;
#define TFR(r) { x0 += x1; x1 = rotl32(x1, (r)); x1 ^= x0; }
    TFR(13) TFR(15) TFR(26) TFR(6)  x0 += k1;  x1 += ks2 + 1u;
    TFR(17) TFR(29) TFR(16) TFR(24) x0 += ks2; x1 += k0  + 2u;
    TFR(13) TFR(15) TFR(26) TFR(6)  x0 += k0;  x1 += k1  + 3u;
    TFR(17) TFR(29) TFR(16) TFR(24) x0 += k1;  x1 += ks2 + 4u;
    TFR(13) TFR(15) TFR(26) TFR(6)  x0 += ks2; x1 += k0  + 5u;
#undef TFR
    o0 = x0; o1 = x1;
}

__device__ __forceinline__ float erfinv_xla(float x) {
    float w = -log1pf(-x * x);
    float p;
    if (w < 5.0f) {
        w -= 2.5f;
        p = 2.81022636e-08f;
        p = fmaf(p, w, 3.43273939e-07f);
        p = fmaf(p, w, -3.5233877e-06f);
        p = fmaf(p, w, -4.39150654e-06f);
        p = fmaf(p, w, 0.00021858087f);
        p = fmaf(p, w, -0.00125372503f);
        p = fmaf(p, w, -0.00417768164f);
        p = fmaf(p, w, 0.246640727f);
        p = fmaf(p, w, 1.50140941f);
    } else {
        w = sqrtf(w) - 3.0f;
        p = -0.000200214257f;
        p = fmaf(p, w, 0.000100950558f);
        p = fmaf(p, w, 0.00134934322f);
        p = fmaf(p, w, -0.00367342844f);
        p = fmaf(p, w, 0.00573950773f);
        p = fmaf(p, w, -0.0076224613f);
        p = fmaf(p, w, 0.00943887047f);
        p = fmaf(p, w, 1.00167406f);
        p = fmaf(p, w, 2.83297682f);
    }
    return p * x;
}

__device__ __forceinline__ float bits_to_normal(uint32_t b) {
    float f = __uint_as_float((b >> 9) | 0x3f800000u) - 1.0f;
    const float minv = -0.99999994f;
    float u = fmaf(f, 2.0f, minv);
    u = fmaxf(u, minv);
    return 1.41421356f * erfinv_xla(u);
}

__global__ void gen_normal_kernel(int which, const int* __restrict__ seed_ptr) {
    int n = which ? (D_N * EXTRA_N) : (D_N * POOL_N);
    int i = blockIdx.x * blockDim.x + threadIdx.x;
    if (i >= n) return;
    uint32_t k0 = 0u;
    uint32_t k1 = (uint32_t)(seed_ptr[0] + (which ? 9991 : 0));
    uint32_t o0, o1;
    threefry2x32(k0, k1, 0u, (uint32_t)i, o0, o1);
    float* out = which ? g_R : g_Apool;
    out[i] = bits_to_normal(o0 ^ o1);
}

/* ------------------------------------------------------------------ */
/* Column means                                                       */
/* ------------------------------------------------------------------ */
__global__ void colmean_kernel(const float* __restrict__ z) {
    __shared__ float2 sm[8][128];
    int x = threadIdx.x, y = threadIdx.y;
    int c = blockIdx.x * 128 + x;
    float s = 0.f, comp = 0.f;
    for (int b = y; b < B_N; b += 8) {
        float v = z[(size_t)b * D_N + c];
        float yv = v - comp;
        float t = s + yv;
        comp = (t - s) - yv;
        s = t;
    }
    sm[y][x] = make_float2(s, comp);
    __syncthreads();
    if (y == 0) {
        double tot = 0.0;
        for (int w = 0; w < 8; w++) {
            float2 p = sm[w][x];
            tot += (double)p.x - (double)p.y;
        }
        g_means[c] = (float)(tot * (1.0 / 2048.0));
    }
}

/* ------------------------------------------------------------------ */
/* Column normalize                                                   */
/* ------------------------------------------------------------------ */
__global__ void norm_cols_kernel(int which) {
    float* A = which ? g_R : g_Apool;
    int nc   = which ? EXTRA_N : POOL_N;
    __shared__ float2 sm[16][64];
    __shared__ float sden[64];
    int x = threadIdx.x, y = threadIdx.y;
    int col = blockIdx.x * 64 + x;

    float s = 0.f, comp = 0.f;
    for (int r = 0; r < 64; r++) {
        int d = y * 64 + r;
        float v = A[(size_t)d * nc + col];
        float v2 = v * v;
        float yv = v2 - comp;
        float t = s + yv;
        comp = (t - s) - yv;
        s = t;
    }
    sm[y][x] = make_float2(s, comp);
    __syncthreads();
    if (y == 0) {
        double tot = 0.0;
        for (int w = 0; w < 16; w++) {
            float2 p = sm[w][x];
            tot += (double)p.x - (double)p.y;
        }
        sden[x] = (float)sqrt(tot) + 1e-12f;
    }
    __syncthreads();
    float den = sden[x];
    for (int r = 0; r < 64; r++) {
        int d = y * 64 + r;
        A[(size_t)d * nc + col] /= den;
    }
}

/* ------------------------------------------------------------------ */
/* GEMM0 (pool): u^T[n][m] = sum_k (z[m][k]-mean[k]) * Apool[k][n]    */
/* 256x128 tile, 512 threads, packed f32x2 FMA, single wave (128 blk) */
/* ------------------------------------------------------------------ */
__global__ void __launch_bounds__(512, 1) gemm0_kernel(const float* __restrict__ z) {
    __shared__ __align__(16) float As[8][BM + 4];
    __shared__ __align__(16) float Bs[8][BN + 4];

    int tid = threadIdx.x;
    int tx = tid & 15;            /* n subtile: 8 cols  */
    int ty = tid >> 4;            /* m subtile: 8 rows, 0..31 */
    int m0 = blockIdx.y * BM, n0 = blockIdx.x * BN;

    int a_row = tid >> 1;         /* 0..255 */
    int a_k4  = (tid & 1) * 4;
    int b_k   = tid >> 6;         /* 0..7 */
    int b_n2  = (tid & 63) * 2;

    const float* Ap = z + (size_t)(m0 + a_row) * D_N + a_k4;
    const float* Bp = g_Apool + (size_t)b_k * POOL_N + n0 + b_n2;

    unsigned long long acc[8][4];
#pragma unroll
    for (int i = 0; i < 8; i++)
#pragma unroll
        for (int jp = 0; jp < 4; jp++) acc[i][jp] = 0ull;

    float4 av = *(const float4*)Ap;
    float4 mv = *(const float4*)(g_means + a_k4);
    float2 bv = *(const float2*)Bp;

    for (int k0 = 0; k0 < D_N; k0 += 8) {
        float4 ac;
        ac.x = av.x - mv.x; ac.y = av.y - mv.y;
        ac.z = av.z - mv.z; ac.w = av.w - mv.w;
        __syncthreads();
        As[a_k4 + 0][a_row] = ac.x;
        As[a_k4 + 1][a_row] = ac.y;
        As[a_k4 + 2][a_row] = ac.z;
        As[a_k4 + 3][a_row] = ac.w;
        *(float2*)&Bs[b_k][b_n2] = bv;
        __syncthreads();
        if (k0 + 8 < D_N) {
            av = *(const float4*)(Ap + k0 + 8);
            mv = *(const float4*)(g_means + k0 + 8 + a_k4);
            bv = *(const float2*)(Bp + (size_t)(k0 + 8) * POOL_N);
        }
#pragma unroll
        for (int kk = 0; kk < 8; kk++) {
            float4 a0 = *(const float4*)&As[kk][ty * 8];
            float4 a1 = *(const float4*)&As[kk][ty * 8 + 4];
            ulonglong2 b0 = *(const ulonglong2*)&Bs[kk][tx * 8];
            ulonglong2 b1 = *(const ulonglong2*)&Bs[kk][tx * 8 + 4];
            unsigned long long a2[8];
            a2[0] = bcast2(a0.x); a2[1] = bcast2(a0.y);
            a2[2] = bcast2(a0.z); a2[3] = bcast2(a0.w);
            a2[4] = bcast2(a1.x); a2[5] = bcast2(a1.y);
            a2[6] = bcast2(a1.z); a2[7] = bcast2(a1.w);
#pragma unroll
            for (int i = 0; i < 8; i++) {
                fma2(acc[i][0], a2[i], b0.x);
                fma2(acc[i][1], a2[i], b0.y);
                fma2(acc[i][2], a2[i], b1.x);
                fma2(acc[i][3], a2[i], b1.y);
            }
        }
    }

#pragma unroll
    for (int jp = 0; jp < 4; jp++) {
        float lo[8], hi[8];
#pragma unroll
        for (int i = 0; i < 8; i++) {
            float2 p = unpk2(acc[i][jp]);
            lo[i] = p.x; hi[i] = p.y;
        }
        int ne = n0 + tx * 8 + 2 * jp;
        float* be = &g_ut[(size_t)ne * B_N + m0 + ty * 8];
        float* bo = &g_ut[(size_t)(ne + 1) * B_N + m0 + ty * 8];
        *(float4*)be       = make_float4(lo[0], lo[1], lo[2], lo[3]);
        *(float4*)(be + 4) = make_float4(lo[4], lo[5], lo[6], lo[7]);
        *(float4*)bo       = make_float4(hi[0], hi[1], hi[2], hi[3]);
        *(float4*)(bo + 4) = make_float4(hi[4], hi[5], hi[6], hi[7]);
    }
}

/* ------------------------------------------------------------------ */
/* GEMM1 (final): u2^T = (z-mean) @ Afin, 128x128 tile               */
/* ------------------------------------------------------------------ */
__global__ void __launch_bounds__(256) gemm1_kernel(const float* __restrict__ z) {
    const float* __restrict__ Bm = g_Afin;
    float*       __restrict__ Ct = g_u2t;
    const int N = AFIN_N, K = D_N, M = B_N;

    __shared__ float As[8][132];
    __shared__ float Bs[8][132];

    int tid = threadIdx.x;
    int tx = tid & 15, ty = tid >> 4;
    int m0 = blockIdx.y * 128, n0 = blockIdx.x * 128;

    int a_row = tid >> 1;
    int a_k4  = (tid & 1) * 4;
    int b_k   = tid >> 5;
    int b_n4  = (tid & 31) * 4;

    const float* Ap = z  + (size_t)(m0 + a_row) * K + a_k4;
    const float* Bp = Bm + (size_t)b_k * N + n0 + b_n4;

    float acc[8][8];
#pragma unroll
    for (int i = 0; i < 8; i++)
#pragma unroll
        for (int j = 0; j < 8; j++) acc[i][j] = 0.f;

    for (int k0 = 0; k0 < K; k0 += 8) {
        float4 av = *(const float4*)(Ap + k0);
        float4 mv = *(const float4*)(g_means + k0 + a_k4);
        float4 bv = *(const float4*)(Bp + (size_t)k0 * N);
        av.x -= mv.x; av.y -= mv.y; av.z -= mv.z; av.w -= mv.w;
        __syncthreads();
        As[a_k4 + 0][a_row] = av.x;
        As[a_k4 + 1][a_row] = av.y;
        As[a_k4 + 2][a_row] = av.z;
        As[a_k4 + 3][a_row] = av.w;
        *(float4*)&Bs[b_k][b_n4] = bv;
        __syncthreads();
#pragma unroll
        for (int kk = 0; kk < 8; kk++) {
            float a[8], b[8];
#pragma unroll
            for (int i = 0; i < 8; i++) a[i] = As[kk][ty * 8 + i];
#pragma unroll
            for (int j = 0; j < 8; j++) b[j] = Bs[kk][tx * 8 + j];
#pragma unroll
            for (int i = 0; i < 8; i++)
#pragma unroll
                for (int j = 0; j < 8; j++)
                    acc[i][j] = fmaf(a[i], b[j], acc[i][j]);
        }
    }
#pragma unroll
    for (int j = 0; j < 8; j++) {
        int n = n0 + tx * 8 + j;
        float4 v0 = make_float4(acc[0][j], acc[1][j], acc[2][j], acc[3][j]);
        float4 v1 = make_float4(acc[4][j], acc[5][j], acc[6][j], acc[7][j]);
        *(float4*)&Ct[(size_t)n * M + m0 + ty * 8]     = v0;
        *(float4*)&Ct[(size_t)n * M + m0 + ty * 8 + 4] = v1;
    }
}

/* ------------------------------------------------------------------ */
/* ECF slice loss                                                     */
/* ------------------------------------------------------------------ */
__device__ __forceinline__ void ecf_sample(float x, float ar[8], float ai[8]) {
    float s1, c1;
    __sincosf(x, &s1, &c1);
    float twoc = c1 + c1;
    float cm = 1.f, sm = 0.f;
    float c = c1, s = s1;
#pragma unroll
    for (int j = 0; j < 8; j++) {
        ar[j] += c; ai[j] += s;
        float cn = fmaf(twoc, c, -cm);
        float sn = fmaf(twoc, s, -sm);
        cm = c; sm = s; c = cn; s = sn;
    }
}

__global__ void __launch_bounds__(256) ecf_kernel(int which) {
    const float*  __restrict__ ut = which ? g_u2t : g_ut;
    double*       __restrict__ L  = which ? g_floss : g_losses;
    int a = blockIdx.x;
    int t = threadIdx.x;
    int lane = t & 31, warp = t >> 5;
    const float4* row4 = (const float4*)(ut + (size_t)a * B_N);

    float ar[8], ai[8];
#pragma unroll
    for (int j = 0; j < 8; j++) { ar[j] = 0.f; ai[j] = 0.f; }

#pragma unroll
    for (int it = 0; it < 2; it++) {
        float4 xv = row4[t + 256 * it];
        ecf_sample(0.625f * xv.x, ar, ai);
        ecf_sample(0.625f * xv.y, ar, ai);
        ecf_sample(0.625f * xv.z, ar, ai);
        ecf_sample(0.625f * xv.w, ar, ai);
    }

    __shared__ float2 sred[8][16];
    __shared__ double sredd[16];
#pragma unroll
    for (int q = 0; q < 16; q++) {
        float hi = (q < 8) ? ar[q] : ai[q - 8];
        float lo = 0.f;
#pragma unroll
        for (int o = 16; o; o >>= 1) {
            float h2 = __shfl_xor_sync(0xffffffffu, hi, o);
            float l2 = __shfl_xor_sync(0xffffffffu, lo, o);
            ff_add(hi, lo, h2, l2);
        }
        if (lane == 0) sred[warp][q] = make_float2(hi, lo);
    }
    __syncthreads();
    if (t < 16) {
        double tot = 0.0;
        for (int w = 0; w < 8; w++) {
            float2 p = sred[w][t];
            tot += (double)p.x + (double)p.y;
        }
        sredd[t] = tot;
    }
    __syncthreads();
    if (t == 0) {
        const double invB = 1.0 / 2048.0;
        double loss = 0.0;
#pragma unroll
        for (int j = 1; j <= 8; j++) {
            double tj = 0.625 * (double)j;
            double ph = exp(-0.5 * tj * tj);
            double re = sredd[j - 1] * invB - ph;
            double im = sredd[8 + j - 1] * invB;
            double integ = (re * re + im * im) * ph;
            loss += ((j == 8) ? 0.625 : 1.25) * integ;
        }
        L[a] = loss;
    }
}

/* ------------------------------------------------------------------ */
/* Bitonic sort                                                       */
/* ------------------------------------------------------------------ */
__global__ void __launch_bounds__(1024) sort_kernel() {
    __shared__ long long sv[2048];
    __shared__ int       si[2048];
    int t = threadIdx.x;
    for (int i = t; i < 2048; i += 1024) {
        sv[i] = __double_as_longlong(g_losses[i]);
        si[i] = i;
    }
    __syncthreads();
    for (int k = 2; k <= 2048; k <<= 1) {
        for (int jj = k >> 1; jj > 0; jj >>= 1) {
            for (int i = t; i < 2048; i += 1024) {
                int ixj = i ^ jj;
                if (ixj > i) {
                    long long va = sv[i], vb = sv[ixj];
                    int       ia = si[i], ib = si[ixj];
                    bool aFirst = (va > vb) || (va == vb && ia < ib);
                    bool dirAsc = ((i & k) == 0);
                    if (aFirst != dirAsc) {
                        sv[i] = vb; sv[ixj] = va;
                        si[i] = ib; si[ixj] = ia;
                    }
                }
            }
            __syncthreads();
        }
    }
    for (int i = t; i < HARD_N; i += 1024) g_ranked[i] = si[i];
}

/* ------------------------------------------------------------------ */
/* GS via Cholesky                                                    */
/* ------------------------------------------------------------------ */
__global__ void gather_kernel() {
    int idx = blockIdx.x * 256 + threadIdx.x;
    int i = idx >> 10, d = idx & 1023;
    g_H[idx] = g_Apool[(size_t)d * POOL_N + g_ranked[i]];
}

__global__ void __launch_bounds__(256) syrk_kernel() {
    int i = blockIdx.x;
    __shared__ float hi[D_N];
    int tid = threadIdx.x;
    *(float4*)&hi[tid * 4] = *(const float4*)&g_H[(size_t)i * D_N + tid * 4];
    __syncthreads();
    int lane = tid & 31, warp = tid >> 5;
    const float4* hi4 = (const float4*)hi;
    for (int j = warp; j < HARD_N; j += 8) {
        const float4* hj = (const float4*)&g_H[(size_t)j * D_N];
        float acc = 0.f;
        for (int d4 = lane; d4 < 256; d4 += 32) {
            float4 a = hi4[d4];
            float4 b = hj[d4];
            acc = fmaf(a.x, b.x, fmaf(a.y, b.y, fmaf(a.z, b.z, fmaf(a.w, b.w, acc))));
        }
#pragma unroll
        for (int o = 16; o; o >>= 1) acc += __shfl_down_sync(0xffffffffu, acc, o);
        if (lane == 0) g_G[i * HARD_N + j] = acc;
    }
}

__global__ void __launch_bounds__(128) cholinv_kernel() {
    extern __shared__ float sbuf[];
    float* sR = sbuf;
    float* sT = sbuf + HARD_N * HARD_N;
    int m = threadIdx.x;
    __shared__ float sdiag;

    for (int k = 0; k < HARD_N; k++) {
        sR[k * HARD_N + m] = g_G[k * HARD_N + m];
        sT[k * HARD_N + m] = 0.f;
    }
    __syncthreads();

    for (int j = 0; j < HARD_N; j++) {
        float s0 = 0.f, s1 = 0.f;
        int k = 0;
        for (; k + 2 <= j; k += 2) {
            s0 = fmaf(sR[k * HARD_N + j],       sR[k * HARD_N + m],       s0);
            s1 = fmaf(sR[(k + 1) * HARD_N + j], sR[(k + 1) * HARD_N + m], s1);
        }
        if (k < j) s0 = fmaf(sR[k * HARD_N + j], sR[k * HARD_N + m], s0);
        float smm = s0 + s1;
        if (m == j) {
            float dd = sR[j * HARD_N + j] - smm;
            float r  = sqrtf(fmaxf(dd, 0.f));
            sdiag = fmaxf(r, 1e-12f);
        }
        __syncthreads();
        float rjj = sdiag;
        if (m > j)       sR[j * HARD_N + m] = (sR[j * HARD_N + m] - smm) / rjj;
        else if (m == j) sR[j * HARD_N + j] = rjj;
        __syncthreads();
    }

    int jc = m;
    sT[jc * HARD_N + jc] = 1.f / sR[jc * HARD_N + jc];
    for (int i = HARD_N - 2; i >= 0; i--) {
        float a0 = 0.f, a1 = 0.f;
        int k = i + 1;
        for (; k + 2 <= HARD_N; k += 2) {
            a0 = fmaf(sR[i * HARD_N + k],     sT[k * HARD_N + jc],       a0);
            a1 = fmaf(sR[i * HARD_N + k + 1], sT[(k + 1) * HARD_N + jc], a1);
        }
        if (k < HARD_N) a0 = fmaf(sR[i * HARD_N + k], sT[k * HARD_N + jc], a0);
        if (i < jc) sT[i * HARD_N + jc] = -(a0 + a1) / sR[i * HARD_N + i];
    }
    __syncthreads();
    for (int k = 0; k < HARD_N; k++)
        g_T[k * HARD_N + m] = sT[k * HARD_N + m];
}

__global__ void __launch_bounds__(256) qht_kernel() {
    int j = threadIdx.x & 127;
    int d = blockIdx.x * 2 + (threadIdx.x >> 7);
    float a0 = 0.f, a1 = 0.f;
    for (int k = 0; k < HARD_N; k += 2) {
        float h0 = g_H[(size_t)k * D_N + d];
        float h1 = g_H[(size_t)(k + 1) * D_N + d];
        a0 = fmaf(h0, g_T[k * HARD_N + j], a0);
        a1 = fmaf(h1, g_T[(k + 1) * HARD_N + j], a1);
    }
    g_Q[(size_t)j * D_N + d] = a0 + a1;
}

/* ------------------------------------------------------------------ */
/* Extra directions                                                   */
/* ------------------------------------------------------------------ */
__global__ void qtr_kernel() {
    int i = blockIdx.x;
    int j = threadIdx.x;
    const float* q = g_Q + (size_t)i * D_N;
    float s = 0.f;
    for (int d = 0; d < D_N; d++)
        s = fmaf(q[d], g_R[(size_t)d * EXTRA_N + j], s);
    g_C[i * EXTRA_N + j] = s;
}

__global__ void subproj_kernel() {
    int idx = blockIdx.x * blockDim.x + threadIdx.x;
    int d = idx >> 6, j = idx & 63;
    float s = 0.f;
    for (int i = 0; i < HARD_N; i++)
        s = fmaf(g_Q[(size_t)i * D_N + d], g_C[i * EXTRA_N + j], s);
    g_R[idx] -= s;
}

__global__ void assemble_kernel() {
    int idx = blockIdx.x * blockDim.x + threadIdx.x;
    int d = idx >> 8, c = idx & 255;
    float v = 0.f;
    if (c < HARD_N)      v = g_Q[(size_t)c * D_N + d];
    else if (c < NFIN)   v = g_R[(size_t)d * EXTRA_N + (c - HARD_N)];
    g_Afin[idx] = v;
}

__global__ void final_kernel(float* __restrict__ out) {
    __shared__ double sh[256];
    int t = threadIdx.x;
    sh[t] = (t < NFIN) ? g_floss[t] : 0.0;
    __syncthreads();
    if (t == 0) {
        double s = 0.0;
        for (int i = 0; i < NFIN; i++) s += sh[i];
        out[0] = (float)((s / 192.0) * 2048.0);
    }
}

/* ------------------------------------------------------------------ */
extern "C" void kernel_launch(void* const* d_in, const int* in_sizes, int n_in,
                              void* d_out, int out_size) {
    const float* z; const int* seed;
    if (in_sizes[0] == 1) { seed = (const int*)d_in[0]; z = (const float*)d_in[1]; }
    else                  { z = (const float*)d_in[0]; seed = (const int*)d_in[1]; }
    float* out = (float*)d_out;

    static int smem_set = 0;
    if (!smem_set) {
        cudaFuncSetAttribute(cholinv_kernel,
                             cudaFuncAttributeMaxDynamicSharedMemorySize,
                             2 * HARD_N * HARD_N * (int)sizeof(float));
        smem_set = 1;
    }

    colmean_kernel<<<8, dim3(128, 8)>>>(z);

    gen_normal_kernel<<<(D_N * POOL_N) / 256, 256>>>(0, seed);
    norm_cols_kernel<<<POOL_N / 64, dim3(64, 16)>>>(0);

    gemm0_kernel<<<dim3(POOL_N / BN, B_N / BM), 512>>>(z);
    ecf_kernel<<<POOL_N, 256>>>(0);

    sort_kernel<<<1, 1024>>>();

    gather_kernel<<<(HARD_N * D_N) / 256, 256>>>();
    syrk_kernel<<<HARD_N, 256>>>();
    cholinv_kernel<<<1, 128, 2 * HARD_N * HARD_N * sizeof(float)>>>();
    qht_kernel<<<D_N / 2, 256>>>();

    gen_normal_kernel<<<(D_N * EXTRA_N) / 256, 256>>>(1, seed);
    norm_cols_kernel<<<1, dim3(64, 16)>>>(1);
    qtr_kernel<<<HARD_N, EXTRA_N>>>();
    subproj_kernel<<<(D_N * EXTRA_N) / 256, 256>>>();
    norm_cols_kernel<<<1, dim3(64, 16)>>>(1);

    assemble_kernel<<<(D_N * AFIN_N) / 256, 256>>>();
    gemm1_kernel<<<dim3(AFIN_N / 128, B_N / 128), 256>>>(z);
    ecf_kernel<<<NFIN, 256>>>(1);

    final_kernel<<<1, 256>>>(out);
}

// round 9
// speedup vs baseline: 4.6108x; 1.1372x over previous
#include <cuda_runtime.h>
#include <stdint.h>

#define B_N    2048
#define D_N    1024
#define POOL_N 2048
#define HARD_N 128
#define EXTRA_N 64
#define AFIN_N 256   /* padded storage; 192 real columns */
#define NFIN   192

#define BM 256
#define BN 128

/* ------------------------------------------------------------------ */
/* Scratch                                                            */
/* ------------------------------------------------------------------ */
__device__ float  g_Apool[D_N * POOL_N];
__device__ float  g_means[D_N];
__device__ float  g_ut[POOL_N * B_N];
__device__ float  g_u2t[AFIN_N * B_N];
__device__ double g_losses[POOL_N];
__device__ int    g_ranked[HARD_N];
__device__ float  g_H[HARD_N * D_N];
__device__ float  g_G[HARD_N * HARD_N];
__device__ float  g_T[HARD_N * HARD_N];
__device__ float  g_Q[HARD_N * D_N];
__device__ float  g_R[D_N * EXTRA_N];
__device__ float  g_C[HARD_N * EXTRA_N];
__device__ float  g_Afin[D_N * AFIN_N];
__device__ double g_floss[NFIN];

/* ---------------- packed f32x2 helpers ---------------------------- */
__device__ __forceinline__ unsigned long long bcast2(float x) {
    unsigned long long r;
    asm("mov.b64 %0, {%1, %1};" : "=l"(r) : "f"(x));
    return r;
}
__device__ __forceinline__ void fma2(unsigned long long& d,
                                     unsigned long long a,
                                     unsigned long long b) {
    asm("fma.rn.f32x2 %0, %1, %2, %0;" : "+l"(d) : "l"(a), "l"(b));
}
__device__ __forceinline__ float2 unpk2(unsigned long long v) {
    float2 r;
    asm("mov.b64 {%0, %1}, %2;" : "=f"(r.x), "=f"(r.y) : "l"(v));
    return r;
}

/* compensated add */
__device__ __forceinline__ void ff_add(float& hi, float& lo, float bhi, float blo) {
    float s  = hi + bhi;
    float bb = s - hi;
    float err = (hi - (s - bb)) + (bhi - bb);
    lo = lo + blo + err;
    hi = s;
}

/* ------------------------------------------------------------------ */
/* JAX threefry2x32 (partitionable)                                   */
/* ------------------------------------------------------------------ */
__device__ __forceinline__ uint32_t rotl32(uint32_t x, int r) {
    return (x << r) | (x >> (32 - r));
}

__device__ __forceinline__ void threefry2x32(uint32_t k0, uint32_t k1,
                                             uint32_t x0, uint32_t x1,
                                             uint32_t& o0, uint32_t& o1) {
    uint32_t ks2 = k0 ^ k1 ^ 0x1BD11BDAu;
    x0 += k0; x1 += k1;
#define TFR(r) { x0 += x1; x1 = rotl32(x1, (r)); x1 ^= x0; }
    TFR(13) TFR(15) TFR(26) TFR(6)  x0 += k1;  x1 += ks2 + 1u;
    TFR(17) TFR(29) TFR(16) TFR(24) x0 += ks2; x1 += k0  + 2u;
    TFR(13) TFR(15) TFR(26) TFR(6)  x0 += k0;  x1 += k1  + 3u;
    TFR(17) TFR(29) TFR(16) TFR(24) x0 += k1;  x1 += ks2 + 4u;
    TFR(13) TFR(15) TFR(26) TFR(6)  x0 += ks2; x1 += k0  + 5u;
#undef TFR
    o0 = x0; o1 = x1;
}

__device__ __forceinline__ float erfinv_xla(float x) {
    float w = -log1pf(-x * x);
    float p;
    if (w < 5.0f) {
        w -= 2.5f;
        p = 2.81022636e-08f;
        p = fmaf(p, w, 3.43273939e-07f);
        p = fmaf(p, w, -3.5233877e-06f);
        p = fmaf(p, w, -4.39150654e-06f);
        p = fmaf(p, w, 0.00021858087f);
        p = fmaf(p, w, -0.00125372503f);
        p = fmaf(p, w, -0.00417768164f);
        p = fmaf(p, w, 0.246640727f);
        p = fmaf(p, w, 1.50140941f);
    } else {
        w = sqrtf(w) - 3.0f;
        p = -0.000200214257f;
        p = fmaf(p, w, 0.000100950558f);
        p = fmaf(p, w, 0.00134934322f);
        p = fmaf(p, w, -0.00367342844f);
        p = fmaf(p, w, 0.00573950773f);
        p = fmaf(p, w, -0.0076224613f);
        p = fmaf(p, w, 0.00943887047f);
        p = fmaf(p, w, 1.00167406f);
        p = fmaf(p, w, 2.83297682f);
    }
    return p * x;
}

__device__ __forceinline__ float bits_to_normal(uint32_t b) {
    float f = __uint_as_float((b >> 9) | 0x3f800000u) - 1.0f;
    const float minv = -0.99999994f;
    float u = fmaf(f, 2.0f, minv);
    u = fmaxf(u, minv);
    return 1.41421356f * erfinv_xla(u);
}

__global__ void gen_normal_kernel(int which, const int* __restrict__ seed_ptr) {
    int n = which ? (D_N * EXTRA_N) : (D_N * POOL_N);
    int i = blockIdx.x * blockDim.x + threadIdx.x;
    if (i >= n) return;
    uint32_t k0 = 0u;
    uint32_t k1 = (uint32_t)(seed_ptr[0] + (which ? 9991 : 0));
    uint32_t o0, o1;
    threefry2x32(k0, k1, 0u, (uint32_t)i, o0, o1);
    float* out = which ? g_R : g_Apool;
    out[i] = bits_to_normal(o0 ^ o1);
}

/* ------------------------------------------------------------------ */
/* Column means                                                       */
/* ------------------------------------------------------------------ */
__global__ void colmean_kernel(const float* __restrict__ z) {
    __shared__ float2 sm[8][128];
    int x = threadIdx.x, y = threadIdx.y;
    int c = blockIdx.x * 128 + x;
    float s = 0.f, comp = 0.f;
    for (int b = y; b < B_N; b += 8) {
        float v = z[(size_t)b * D_N + c];
        float yv = v - comp;
        float t = s + yv;
        comp = (t - s) - yv;
        s = t;
    }
    sm[y][x] = make_float2(s, comp);
    __syncthreads();
    if (y == 0) {
        double tot = 0.0;
        for (int w = 0; w < 8; w++) {
            float2 p = sm[w][x];
            tot += (double)p.x - (double)p.y;
        }
        g_means[c] = (float)(tot * (1.0 / 2048.0));
    }
}

/* ------------------------------------------------------------------ */
/* Column normalize                                                   */
/* ------------------------------------------------------------------ */
__global__ void norm_cols_kernel(int which) {
    float* A = which ? g_R : g_Apool;
    int nc   = which ? EXTRA_N : POOL_N;
    __shared__ float2 sm[16][64];
    __shared__ float sden[64];
    int x = threadIdx.x, y = threadIdx.y;
    int col = blockIdx.x * 64 + x;

    float s = 0.f, comp = 0.f;
    for (int r = 0; r < 64; r++) {
        int d = y * 64 + r;
        float v = A[(size_t)d * nc + col];
        float v2 = v * v;
        float yv = v2 - comp;
        float t = s + yv;
        comp = (t - s) - yv;
        s = t;
    }
    sm[y][x] = make_float2(s, comp);
    __syncthreads();
    if (y == 0) {
        double tot = 0.0;
        for (int w = 0; w < 16; w++) {
            float2 p = sm[w][x];
            tot += (double)p.x - (double)p.y;
        }
        sden[x] = (float)sqrt(tot) + 1e-12f;
    }
    __syncthreads();
    float den = sden[x];
    for (int r = 0; r < 64; r++) {
        int d = y * 64 + r;
        A[(size_t)d * nc + col] /= den;
    }
}

/* ------------------------------------------------------------------ */
/* GEMM0 (pool): 256x128 tile, 512 thr, f32x2 — at pipe roofline     */
/* ------------------------------------------------------------------ */
__global__ void __launch_bounds__(512, 1) gemm0_kernel(const float* __restrict__ z) {
    __shared__ __align__(16) float As[8][BM + 4];
    __shared__ __align__(16) float Bs[8][BN + 4];

    int tid = threadIdx.x;
    int tx = tid & 15;
    int ty = tid >> 4;
    int m0 = blockIdx.y * BM, n0 = blockIdx.x * BN;

    int a_row = tid >> 1;
    int a_k4  = (tid & 1) * 4;
    int b_k   = tid >> 6;
    int b_n2  = (tid & 63) * 2;

    const float* Ap = z + (size_t)(m0 + a_row) * D_N + a_k4;
    const float* Bp = g_Apool + (size_t)b_k * POOL_N + n0 + b_n2;

    unsigned long long acc[8][4];
#pragma unroll
    for (int i = 0; i < 8; i++)
#pragma unroll
        for (int jp = 0; jp < 4; jp++) acc[i][jp] = 0ull;

    float4 av = *(const float4*)Ap;
    float4 mv = *(const float4*)(g_means + a_k4);
    float2 bv = *(const float2*)Bp;

    for (int k0 = 0; k0 < D_N; k0 += 8) {
        float4 ac;
        ac.x = av.x - mv.x; ac.y = av.y - mv.y;
        ac.z = av.z - mv.z; ac.w = av.w - mv.w;
        __syncthreads();
        As[a_k4 + 0][a_row] = ac.x;
        As[a_k4 + 1][a_row] = ac.y;
        As[a_k4 + 2][a_row] = ac.z;
        As[a_k4 + 3][a_row] = ac.w;
        *(float2*)&Bs[b_k][b_n2] = bv;
        __syncthreads();
        if (k0 + 8 < D_N) {
            av = *(const float4*)(Ap + k0 + 8);
            mv = *(const float4*)(g_means + k0 + 8 + a_k4);
            bv = *(const float2*)(Bp + (size_t)(k0 + 8) * POOL_N);
        }
#pragma unroll
        for (int kk = 0; kk < 8; kk++) {
            float4 a0 = *(const float4*)&As[kk][ty * 8];
            float4 a1 = *(const float4*)&As[kk][ty * 8 + 4];
            ulonglong2 b0 = *(const ulonglong2*)&Bs[kk][tx * 8];
            ulonglong2 b1 = *(const ulonglong2*)&Bs[kk][tx * 8 + 4];
            unsigned long long a2[8];
            a2[0] = bcast2(a0.x); a2[1] = bcast2(a0.y);
            a2[2] = bcast2(a0.z); a2[3] = bcast2(a0.w);
            a2[4] = bcast2(a1.x); a2[5] = bcast2(a1.y);
            a2[6] = bcast2(a1.z); a2[7] = bcast2(a1.w);
#pragma unroll
            for (int i = 0; i < 8; i++) {
                fma2(acc[i][0], a2[i], b0.x);
                fma2(acc[i][1], a2[i], b0.y);
                fma2(acc[i][2], a2[i], b1.x);
                fma2(acc[i][3], a2[i], b1.y);
            }
        }
    }

#pragma unroll
    for (int jp = 0; jp < 4; jp++) {
        float lo[8], hi[8];
#pragma unroll
        for (int i = 0; i < 8; i++) {
            float2 p = unpk2(acc[i][jp]);
            lo[i] = p.x; hi[i] = p.y;
        }
        int ne = n0 + tx * 8 + 2 * jp;
        float* be = &g_ut[(size_t)ne * B_N + m0 + ty * 8];
        float* bo = &g_ut[(size_t)(ne + 1) * B_N + m0 + ty * 8];
        *(float4*)be       = make_float4(lo[0], lo[1], lo[2], lo[3]);
        *(float4*)(be + 4) = make_float4(lo[4], lo[5], lo[6], lo[7]);
        *(float4*)bo       = make_float4(hi[0], hi[1], hi[2], hi[3]);
        *(float4*)(bo + 4) = make_float4(hi[4], hi[5], hi[6], hi[7]);
    }
}

/* ------------------------------------------------------------------ */
/* GEMM1 (final): 64x64 tiles, f32x2, 96 blocks over 192 real cols   */
/* u2^T[n][m] = sum_k (z[m][k]-mean[k]) * Afin[k][n]                  */
/* ------------------------------------------------------------------ */
__global__ void __launch_bounds__(256) gemm1_kernel(const float* __restrict__ z) {
    __shared__ __align__(16) float As[16][68];
    __shared__ __align__(16) float Bs[16][68];

    int tid = threadIdx.x;
    int tx = tid & 15, ty = tid >> 4;
    int m0 = blockIdx.y * 64, n0 = blockIdx.x * 64;

    int a_row = tid & 63;          /* 0..63 */
    int a_k4  = (tid >> 6) * 4;    /* 0,4,8,12 */
    int b_k   = tid >> 4;          /* 0..15 */
    int b_n4  = (tid & 15) * 4;

    const float* Ap = z + (size_t)(m0 + a_row) * D_N + a_k4;
    const float* Bp = g_Afin + (size_t)b_k * AFIN_N + n0 + b_n4;

    unsigned long long acc[4][2];
#pragma unroll
    for (int i = 0; i < 4; i++) { acc[i][0] = 0ull; acc[i][1] = 0ull; }

    for (int k0 = 0; k0 < D_N; k0 += 16) {
        float4 av = *(const float4*)(Ap + k0);
        float4 mv = *(const float4*)(g_means + k0 + a_k4);
        float4 bv = *(const float4*)(Bp + (size_t)k0 * AFIN_N);
        av.x -= mv.x; av.y -= mv.y; av.z -= mv.z; av.w -= mv.w;
        __syncthreads();
        As[a_k4 + 0][a_row] = av.x;
        As[a_k4 + 1][a_row] = av.y;
        As[a_k4 + 2][a_row] = av.z;
        As[a_k4 + 3][a_row] = av.w;
        *(float4*)&Bs[b_k][b_n4] = bv;
        __syncthreads();
#pragma unroll
        for (int kk = 0; kk < 16; kk++) {
            float4 a = *(const float4*)&As[kk][ty * 4];
            ulonglong2 b = *(const ulonglong2*)&Bs[kk][tx * 4];
            unsigned long long a2[4];
            a2[0] = bcast2(a.x); a2[1] = bcast2(a.y);
            a2[2] = bcast2(a.z); a2[3] = bcast2(a.w);
#pragma unroll
            for (int i = 0; i < 4; i++) {
                fma2(acc[i][0], a2[i], b.x);
                fma2(acc[i][1], a2[i], b.y);
            }
        }
    }

#pragma unroll
    for (int jp = 0; jp < 2; jp++) {
        int ne = n0 + tx * 4 + 2 * jp;
#pragma unroll
        for (int i = 0; i < 4; i++) {
            float2 p = unpk2(acc[i][jp]);
            int m = m0 + ty * 4 + i;
            g_u2t[(size_t)ne * B_N + m]       = p.x;
            g_u2t[(size_t)(ne + 1) * B_N + m] = p.y;
        }
    }
}

/* ------------------------------------------------------------------ */
/* ECF slice loss                                                     */
/* ------------------------------------------------------------------ */
__device__ __forceinline__ void ecf_sample(float x, float ar[8], float ai[8]) {
    float s1, c1;
    __sincosf(x, &s1, &c1);
    float twoc = c1 + c1;
    float cm = 1.f, sm = 0.f;
    float c = c1, s = s1;
#pragma unroll
    for (int j = 0; j < 8; j++) {
        ar[j] += c; ai[j] += s;
        float cn = fmaf(twoc, c, -cm);
        float sn = fmaf(twoc, s, -sm);
        cm = c; sm = s; c = cn; s = sn;
    }
}

__global__ void __launch_bounds__(256) ecf_kernel(int which) {
    const float*  __restrict__ ut = which ? g_u2t : g_ut;
    double*       __restrict__ L  = which ? g_floss : g_losses;
    int a = blockIdx.x;
    int t = threadIdx.x;
    int lane = t & 31, warp = t >> 5;
    const float4* row4 = (const float4*)(ut + (size_t)a * B_N);

    float ar[8], ai[8];
#pragma unroll
    for (int j = 0; j < 8; j++) { ar[j] = 0.f; ai[j] = 0.f; }

#pragma unroll
    for (int it = 0; it < 2; it++) {
        float4 xv = row4[t + 256 * it];
        ecf_sample(0.625f * xv.x, ar, ai);
        ecf_sample(0.625f * xv.y, ar, ai);
        ecf_sample(0.625f * xv.z, ar, ai);
        ecf_sample(0.625f * xv.w, ar, ai);
    }

    __shared__ float2 sred[8][16];
    __shared__ double sredd[16];
#pragma unroll
    for (int q = 0; q < 16; q++) {
        float hi = (q < 8) ? ar[q] : ai[q - 8];
        float lo = 0.f;
#pragma unroll
        for (int o = 16; o; o >>= 1) {
            float h2 = __shfl_xor_sync(0xffffffffu, hi, o);
            float l2 = __shfl_xor_sync(0xffffffffu, lo, o);
            ff_add(hi, lo, h2, l2);
        }
        if (lane == 0) sred[warp][q] = make_float2(hi, lo);
    }
    __syncthreads();
    if (t < 16) {
        double tot = 0.0;
        for (int w = 0; w < 8; w++) {
            float2 p = sred[w][t];
            tot += (double)p.x + (double)p.y;
        }
        sredd[t] = tot;
    }
    __syncthreads();
    if (t == 0) {
        const double invB = 1.0 / 2048.0;
        double loss = 0.0;
#pragma unroll
        for (int j = 1; j <= 8; j++) {
            double tj = 0.625 * (double)j;
            double ph = exp(-0.5 * tj * tj);
            double re = sredd[j - 1] * invB - ph;
            double im = sredd[8 + j - 1] * invB;
            double integ = (re * re + im * im) * ph;
            loss += ((j == 8) ? 0.625 : 1.25) * integ;
        }
        L[a] = loss;
    }
}

/* ------------------------------------------------------------------ */
/* Bitonic sort                                                       */
/* ------------------------------------------------------------------ */
__global__ void __launch_bounds__(1024) sort_kernel() {
    __shared__ long long sv[2048];
    __shared__ int       si[2048];
    int t = threadIdx.x;
    for (int i = t; i < 2048; i += 1024) {
        sv[i] = __double_as_longlong(g_losses[i]);
        si[i] = i;
    }
    __syncthreads();
    for (int k = 2; k <= 2048; k <<= 1) {
        for (int jj = k >> 1; jj > 0; jj >>= 1) {
            for (int i = t; i < 2048; i += 1024) {
                int ixj = i ^ jj;
                if (ixj > i) {
                    long long va = sv[i], vb = sv[ixj];
                    int       ia = si[i], ib = si[ixj];
                    bool aFirst = (va > vb) || (va == vb && ia < ib);
                    bool dirAsc = ((i & k) == 0);
                    if (aFirst != dirAsc) {
                        sv[i] = vb; sv[ixj] = va;
                        si[i] = ib; si[ixj] = ia;
                    }
                }
            }
            __syncthreads();
        }
    }
    for (int i = t; i < HARD_N; i += 1024) g_ranked[i] = si[i];
}

/* ------------------------------------------------------------------ */
/* GS via Cholesky                                                    */
/* ------------------------------------------------------------------ */
__global__ void gather_kernel() {
    int idx = blockIdx.x * 256 + threadIdx.x;
    int i = idx >> 10, d = idx & 1023;
    g_H[idx] = g_Apool[(size_t)d * POOL_N + g_ranked[i]];
}

__global__ void __launch_bounds__(256) syrk_kernel() {
    int i = blockIdx.x;
    __shared__ float hi[D_N];
    int tid = threadIdx.x;
    *(float4*)&hi[tid * 4] = *(const float4*)&g_H[(size_t)i * D_N + tid * 4];
    __syncthreads();
    int lane = tid & 31, warp = tid >> 5;
    const float4* hi4 = (const float4*)hi;
    for (int j = warp; j < HARD_N; j += 8) {
        const float4* hj = (const float4*)&g_H[(size_t)j * D_N];
        float acc = 0.f;
        for (int d4 = lane; d4 < 256; d4 += 32) {
            float4 a = hi4[d4];
            float4 b = hj[d4];
            acc = fmaf(a.x, b.x, fmaf(a.y, b.y, fmaf(a.z, b.z, fmaf(a.w, b.w, acc))));
        }
#pragma unroll
        for (int o = 16; o; o >>= 1) acc += __shfl_down_sync(0xffffffffu, acc, o);
        if (lane == 0) g_G[i * HARD_N + j] = acc;
    }
}

__global__ void __launch_bounds__(128) cholinv_kernel() {
    extern __shared__ float sbuf[];
    float* sR = sbuf;
    float* sT = sbuf + HARD_N * HARD_N;
    int m = threadIdx.x;
    __shared__ float sdiag;

    for (int k = 0; k < HARD_N; k++) {
        sR[k * HARD_N + m] = g_G[k * HARD_N + m];
        sT[k * HARD_N + m] = 0.f;
    }
    __syncthreads();

    for (int j = 0; j < HARD_N; j++) {
        float s0 = 0.f, s1 = 0.f;
        int k = 0;
        for (; k + 2 <= j; k += 2) {
            s0 = fmaf(sR[k * HARD_N + j],       sR[k * HARD_N + m],       s0);
            s1 = fmaf(sR[(k + 1) * HARD_N + j], sR[(k + 1) * HARD_N + m], s1);
        }
        if (k < j) s0 = fmaf(sR[k * HARD_N + j], sR[k * HARD_N + m], s0);
        float smm = s0 + s1;
        if (m == j) {
            float dd = sR[j * HARD_N + j] - smm;
            float r  = sqrtf(fmaxf(dd, 0.f));
            sdiag = fmaxf(r, 1e-12f);
        }
        __syncthreads();
        float rjj = sdiag;
        if (m > j)       sR[j * HARD_N + m] = (sR[j * HARD_N + m] - smm) / rjj;
        else if (m == j) sR[j * HARD_N + j] = rjj;
        __syncthreads();
    }

    int jc = m;
    sT[jc * HARD_N + jc] = 1.f / sR[jc * HARD_N + jc];
    for (int i = HARD_N - 2; i >= 0; i--) {
        float a0 = 0.f, a1 = 0.f;
        int k = i + 1;
        for (; k + 2 <= HARD_N; k += 2) {
            a0 = fmaf(sR[i * HARD_N + k],     sT[k * HARD_N + jc],       a0);
            a1 = fmaf(sR[i * HARD_N + k + 1], sT[(k + 1) * HARD_N + jc], a1);
        }
        if (k < HARD_N) a0 = fmaf(sR[i * HARD_N + k], sT[k * HARD_N + jc], a0);
        if (i < jc) sT[i * HARD_N + jc] = -(a0 + a1) / sR[i * HARD_N + i];
    }
    __syncthreads();
    for (int k = 0; k < HARD_N; k++)
        g_T[k * HARD_N + m] = sT[k * HARD_N + m];
}

__global__ void __launch_bounds__(256) qht_kernel() {
    int j = threadIdx.x & 127;
    int d = blockIdx.x * 2 + (threadIdx.x >> 7);
    float a0 = 0.f, a1 = 0.f;
    for (int k = 0; k < HARD_N; k += 2) {
        float h0 = g_H[(size_t)k * D_N + d];
        float h1 = g_H[(size_t)(k + 1) * D_N + d];
        a0 = fmaf(h0, g_T[k * HARD_N + j], a0);
        a1 = fmaf(h1, g_T[(k + 1) * HARD_N + j], a1);
    }
    g_Q[(size_t)j * D_N + d] = a0 + a1;
}

/* ------------------------------------------------------------------ */
/* Extra directions                                                   */
/* ------------------------------------------------------------------ */
__global__ void qtr_kernel() {
    int i = blockIdx.x;
    int j = threadIdx.x;
    const float* q = g_Q + (size_t)i * D_N;
    float s = 0.f;
    for (int d = 0; d < D_N; d++)
        s = fmaf(q[d], g_R[(size_t)d * EXTRA_N + j], s);
    g_C[i * EXTRA_N + j] = s;
}

__global__ void subproj_kernel() {
    int idx = blockIdx.x * blockDim.x + threadIdx.x;
    int d = idx >> 6, j = idx & 63;
    float s = 0.f;
    for (int i = 0; i < HARD_N; i++)
        s = fmaf(g_Q[(size_t)i * D_N + d], g_C[i * EXTRA_N + j], s);
    g_R[idx] -= s;
}

__global__ void assemble_kernel() {
    int idx = blockIdx.x * blockDim.x + threadIdx.x;
    int d = idx >> 8, c = idx & 255;
    float v = 0.f;
    if (c < HARD_N)      v = g_Q[(size_t)c * D_N + d];
    else if (c < NFIN)   v = g_R[(size_t)d * EXTRA_N + (c - HARD_N)];
    g_Afin[idx] = v;
}

__global__ void final_kernel(float* __restrict__ out) {
    __shared__ double sh[256];
    int t = threadIdx.x;
    sh[t] = (t < NFIN) ? g_floss[t] : 0.0;
    __syncthreads();
    if (t == 0) {
        double s = 0.0;
        for (int i = 0; i < NFIN; i++) s += sh[i];
        out[0] = (float)((s / 192.0) * 2048.0);
    }
}

/* ------------------------------------------------------------------ */
extern "C" void kernel_launch(void* const* d_in, const int* in_sizes, int n_in,
                              void* d_out, int out_size) {
    const float* z; const int* seed;
    if (in_sizes[0] == 1) { seed = (const int*)d_in[0]; z = (const float*)d_in[1]; }
    else                  { z = (const float*)d_in[0]; seed = (const int*)d_in[1]; }
    float* out = (float*)d_out;

    static int smem_set = 0;
    if (!smem_set) {
        cudaFuncSetAttribute(cholinv_kernel,
                             cudaFuncAttributeMaxDynamicSharedMemorySize,
                             2 * HARD_N * HARD_N * (int)sizeof(float));
        smem_set = 1;
    }

    colmean_kernel<<<8, dim3(128, 8)>>>(z);

    gen_normal_kernel<<<(D_N * POOL_N) / 256, 256>>>(0, seed);
    norm_cols_kernel<<<POOL_N / 64, dim3(64, 16)>>>(0);

    gemm0_kernel<<<dim3(POOL_N / BN, B_N / BM), 512>>>(z);
    ecf_kernel<<<POOL_N, 256>>>(0);

    sort_kernel<<<1, 1024>>>();

    gather_kernel<<<(HARD_N * D_N) / 256, 256>>>();
    syrk_kernel<<<HARD_N, 256>>>();
    cholinv_kernel<<<1, 128, 2 * HARD_N * HARD_N * sizeof(float)>>>();
    qht_kernel<<<D_N / 2, 256>>>();

    gen_normal_kernel<<<(D_N * EXTRA_N) / 256, 256>>>(1, seed);
    norm_cols_kernel<<<1, dim3(64, 16)>>>(1);
    qtr_kernel<<<HARD_N, EXTRA_N>>>();
    subproj_kernel<<<(D_N * EXTRA_N) / 256, 256>>>();
    norm_cols_kernel<<<1, dim3(64, 16)>>>(1);

    assemble_kernel<<<(D_N * AFIN_N) / 256, 256>>>();
    gemm1_kernel<<<dim3(NFIN / 64, B_N / 64), 256>>>(z);
    ecf_kernel<<<NFIN, 256>>>(1);

    final_kernel<<<1, 256>>>(out);
}

// round 11
// speedup vs baseline: 4.6195x; 1.0019x over previous
#include <cuda_runtime.h>
#include <stdint.h>

#define B_N    2048
#define D_N    1024
#define POOL_N 2048
#define HARD_N 128
#define EXTRA_N 64
#define AFIN_N 256
#define NFIN   192

#define BM 256
#define BN 128

/* ------------------------------------------------------------------ */
/* Scratch                                                            */
/* ------------------------------------------------------------------ */
__device__ float  g_Apool[D_N * POOL_N];
__device__ float  g_means[D_N];
__device__ float  g_ut[POOL_N * B_N];
__device__ float  g_u2t[AFIN_N * B_N];
__device__ double g_losses[POOL_N];
__device__ int    g_ranked[HARD_N];
__device__ float  g_H[HARD_N * D_N];
__device__ float  g_G[HARD_N * HARD_N];
__device__ float  g_T[HARD_N * HARD_N];
__device__ float  g_Q[HARD_N * D_N];
__device__ float  g_R[D_N * EXTRA_N];
__device__ float  g_C[HARD_N * EXTRA_N];
__device__ float  g_Afin[D_N * AFIN_N];
__device__ double g_floss[NFIN];

/* ---------------- packed f32x2 helpers ---------------------------- */
__device__ __forceinline__ unsigned long long bcast2(float x) {
    unsigned long long r;
    asm("mov.b64 %0, {%1, %1};" : "=l"(r) : "f"(x));
    return r;
}
__device__ __forceinline__ void fma2(unsigned long long& d,
                                     unsigned long long a,
                                     unsigned long long b) {
    asm("fma.rn.f32x2 %0, %1, %2, %0;" : "+l"(d) : "l"(a), "l"(b));
}
__device__ __forceinline__ float2 unpk2(unsigned long long v) {
    float2 r;
    asm("mov.b64 {%0, %1}, %2;" : "=f"(r.x), "=f"(r.y) : "l"(v));
    return r;
}
__device__ __forceinline__ void ff_add(float& hi, float& lo, float bhi, float blo) {
    float s  = hi + bhi;
    float bb = s - hi;
    float err = (hi - (s - bb)) + (bhi - bb);
    lo = lo + blo + err;
    hi = s;
}

/* ------------------------------------------------------------------ */
/* JAX threefry2x32 (partitionable)                                   */
/* ------------------------------------------------------------------ */
__device__ __forceinline__ uint32_t rotl32(uint32_t x, int r) {
    return (x << r) | (x >> (32 - r));
}
__device__ __forceinline__ void threefry2x32(uint32_t k0, uint32_t k1,
                                             uint32_t x0, uint32_t x1,
                                             uint32_t& o0, uint32_t& o1) {
    uint32_t ks2 = k0 ^ k1 ^ 0x1BD11BDAu;
    x0 += k0; x1 += k1;
#define TFR(r) { x0 += x1; x1 = rotl32(x1, (r)); x1 ^= x0; }
    TFR(13) TFR(15) TFR(26) TFR(6)  x0 += k1;  x1 += ks2 + 1u;
    TFR(17) TFR(29) TFR(16) TFR(24) x0 += ks2; x1 += k0  + 2u;
    TFR(13) TFR(15) TFR(26) TFR(6)  x0 += k0;  x1 += k1  + 3u;
    TFR(17) TFR(29) TFR(16) TFR(24) x0 += k1;  x1 += ks2 + 4u;
    TFR(13) TFR(15) TFR(26) TFR(6)  x0 += ks2; x1 += k0  + 5u;
#undef TFR
    o0 = x0; o1 = x1;
}
__device__ __forceinline__ float erfinv_xla(float x) {
    float w = -log1pf(-x * x);
    float p;
    if (w < 5.0f) {
        w -= 2.5f;
        p = 2.81022636e-08f;
        p = fmaf(p, w, 3.43273939e-07f);
        p = fmaf(p, w, -3.5233877e-06f);
        p = fmaf(p, w, -4.39150654e-06f);
        p = fmaf(p, w, 0.00021858087f);
        p = fmaf(p, w, -0.00125372503f);
        p = fmaf(p, w, -0.00417768164f);
        p = fmaf(p, w, 0.246640727f);
        p = fmaf(p, w, 1.50140941f);
    } else {
        w = sqrtf(w) - 3.0f;
        p = -0.000200214257f;
        p = fmaf(p, w, 0.000100950558f);
        p = fmaf(p, w, 0.00134934322f);
        p = fmaf(p, w, -0.00367342844f);
        p = fmaf(p, w, 0.00573950773f);
        p = fmaf(p, w, -0.0076224613f);
        p = fmaf(p, w, 0.00943887047f);
        p = fmaf(p, w, 1.00167406f);
        p = fmaf(p, w, 2.83297682f);
    }
    return p * x;
}
__device__ __forceinline__ float bits_to_normal(uint32_t b) {
    float f = __uint_as_float((b >> 9) | 0x3f800000u) - 1.0f;
    const float minv = -0.99999994f;
    float u = fmaf(f, 2.0f, minv);
    u = fmaxf(u, minv);
    return 1.41421356f * erfinv_xla(u);
}

/* ------------------------------------------------------------------ */
/* Fused setup: pool gen (blocks 0..8191), colmean (8192..8207),      */
/* extra gen (8208..8719)                                             */
/* ------------------------------------------------------------------ */
#define SETUP_POOL_BLKS  (D_N * POOL_N / 256)         /* 8192 */
#define SETUP_CM_BLKS    16
#define SETUP_EXTRA_BLKS (D_N * EXTRA_N / 256)        /* 512  */

__global__ void __launch_bounds__(256) setup_kernel(const float* __restrict__ z,
                                                    const int* __restrict__ seed_ptr) {
    int b = blockIdx.x;
    if (b < SETUP_POOL_BLKS) {
        int i = b * 256 + threadIdx.x;
        uint32_t k1 = (uint32_t)seed_ptr[0];
        uint32_t o0, o1;
        threefry2x32(0u, k1, 0u, (uint32_t)i, o0, o1);
        g_Apool[i] = bits_to_normal(o0 ^ o1);
    } else if (b < SETUP_POOL_BLKS + SETUP_CM_BLKS) {
        __shared__ float2 sm[4][64];
        int xb = b - SETUP_POOL_BLKS;
        int x = threadIdx.x & 63, y = threadIdx.x >> 6;
        int c = xb * 64 + x;
        float s = 0.f, comp = 0.f;
        for (int r = y; r < B_N; r += 4) {
            float v = z[(size_t)r * D_N + c];
            float yv = v - comp;
            float t = s + yv;
            comp = (t - s) - yv;
            s = t;
        }
        sm[y][x] = make_float2(s, comp);
        __syncthreads();
        if (y == 0) {
            double tot = 0.0;
            for (int w = 0; w < 4; w++) {
                float2 p = sm[w][x];
                tot += (double)p.x - (double)p.y;
            }
            g_means[c] = (float)(tot * (1.0 / 2048.0));
        }
    } else {
        int i = (b - SETUP_POOL_BLKS - SETUP_CM_BLKS) * 256 + threadIdx.x;
        uint32_t k1 = (uint32_t)(seed_ptr[0] + 9991);
        uint32_t o0, o1;
        threefry2x32(0u, k1, 0u, (uint32_t)i, o0, o1);
        g_R[i] = bits_to_normal(o0 ^ o1);
    }
}

/* ------------------------------------------------------------------ */
/* Column normalize: blocks 0..31 pool, block 32 extra (R)            */
/* ------------------------------------------------------------------ */
__device__ __forceinline__ void norm_cols_body(float* A, int nc, int col) {
    __shared__ float2 sm[16][64];
    __shared__ float sden[64];
    int x = threadIdx.x, y = threadIdx.y;
    float s = 0.f, comp = 0.f;
    for (int r = 0; r < 64; r++) {
        int d = y * 64 + r;
        float v = A[(size_t)d * nc + col];
        float v2 = v * v;
        float yv = v2 - comp;
        float t = s + yv;
        comp = (t - s) - yv;
        s = t;
    }
    sm[y][x] = make_float2(s, comp);
    __syncthreads();
    if (y == 0) {
        double tot = 0.0;
        for (int w = 0; w < 16; w++) {
            float2 p = sm[w][x];
            tot += (double)p.x - (double)p.y;
        }
        sden[x] = (float)sqrt(tot) + 1e-12f;
    }
    __syncthreads();
    float den = sden[x];
    for (int r = 0; r < 64; r++) {
        int d = y * 64 + r;
        A[(size_t)d * nc + col] /= den;
    }
}

__global__ void norm_comb_kernel() {
    if (blockIdx.x < 32)
        norm_cols_body(g_Apool, POOL_N, blockIdx.x * 64 + threadIdx.x);
    else
        norm_cols_body(g_R, EXTRA_N, threadIdx.x);
}

__global__ void norm_cols_kernel(int which) {
    float* A = which ? g_R : g_Apool;
    int nc   = which ? EXTRA_N : POOL_N;
    norm_cols_body(A, nc, blockIdx.x * 64 + threadIdx.x);
}

/* ------------------------------------------------------------------ */
/* GEMM0: 256x128 tile, 512 thr, f32x2, double-buffered smem          */
/* ------------------------------------------------------------------ */
__global__ void __launch_bounds__(512, 1) gemm0_kernel(const float* __restrict__ z) {
    __shared__ __align__(16) float As[2][8][BM + 4];
    __shared__ __align__(16) float Bs[2][8][BN + 4];

    int tid = threadIdx.x;
    int tx = tid & 15;
    int ty = tid >> 4;
    int m0 = blockIdx.y * BM, n0 = blockIdx.x * BN;

    int a_row = tid >> 1;
    int a_k4  = (tid & 1) * 4;
    int b_k   = tid >> 6;
    int b_n2  = (tid & 63) * 2;

    const float* Ap = z + (size_t)(m0 + a_row) * D_N + a_k4;
    const float* Bp = g_Apool + (size_t)b_k * POOL_N + n0 + b_n2;

    unsigned long long acc[8][4];
#pragma unroll
    for (int i = 0; i < 8; i++)
#pragma unroll
        for (int jp = 0; jp < 4; jp++) acc[i][jp] = 0ull;

    float4 av = *(const float4*)Ap;
    float4 mv = *(const float4*)(g_means + a_k4);
    float2 bv = *(const float2*)Bp;

    for (int c = 0; c < D_N / 8; c++) {
        int buf = c & 1;
        As[buf][a_k4 + 0][a_row] = av.x - mv.x;
        As[buf][a_k4 + 1][a_row] = av.y - mv.y;
        As[buf][a_k4 + 2][a_row] = av.z - mv.z;
        As[buf][a_k4 + 3][a_row] = av.w - mv.w;
        *(float2*)&Bs[buf][b_k][b_n2] = bv;
        __syncthreads();
        if (c + 1 < D_N / 8) {
            int k0 = (c + 1) * 8;
            av = *(const float4*)(Ap + k0);
            mv = *(const float4*)(g_means + k0 + a_k4);
            bv = *(const float2*)(Bp + (size_t)k0 * POOL_N);
        }
#pragma unroll
        for (int kk = 0; kk < 8; kk++) {
            float4 a0 = *(const float4*)&As[buf][kk][ty * 8];
            float4 a1 = *(const float4*)&As[buf][kk][ty * 8 + 4];
            ulonglong2 b0 = *(const ulonglong2*)&Bs[buf][kk][tx * 8];
            ulonglong2 b1 = *(const ulonglong2*)&Bs[buf][kk][tx * 8 + 4];
            unsigned long long a2[8];
            a2[0] = bcast2(a0.x); a2[1] = bcast2(a0.y);
            a2[2] = bcast2(a0.z); a2[3] = bcast2(a0.w);
            a2[4] = bcast2(a1.x); a2[5] = bcast2(a1.y);
            a2[6] = bcast2(a1.z); a2[7] = bcast2(a1.w);
#pragma unroll
            for (int i = 0; i < 8; i++) {
                fma2(acc[i][0], a2[i], b0.x);
                fma2(acc[i][1], a2[i], b0.y);
                fma2(acc[i][2], a2[i], b1.x);
                fma2(acc[i][3], a2[i], b1.y);
            }
        }
    }

#pragma unroll
    for (int jp = 0; jp < 4; jp++) {
        float lo[8], hi[8];
#pragma unroll
        for (int i = 0; i < 8; i++) {
            float2 p = unpk2(acc[i][jp]);
            lo[i] = p.x; hi[i] = p.y;
        }
        int ne = n0 + tx * 8 + 2 * jp;
        float* be = &g_ut[(size_t)ne * B_N + m0 + ty * 8];
        float* bo = &g_ut[(size_t)(ne + 1) * B_N + m0 + ty * 8];
        *(float4*)be       = make_float4(lo[0], lo[1], lo[2], lo[3]);
        *(float4*)(be + 4) = make_float4(lo[4], lo[5], lo[6], lo[7]);
        *(float4*)bo       = make_float4(hi[0], hi[1], hi[2], hi[3]);
        *(float4*)(bo + 4) = make_float4(hi[4], hi[5], hi[6], hi[7]);
    }
}

/* ------------------------------------------------------------------ */
/* GEMM1 (final): 64x64 tiles, f32x2                                  */
/* ------------------------------------------------------------------ */
__global__ void __launch_bounds__(256) gemm1_kernel(const float* __restrict__ z) {
    __shared__ __align__(16) float As[16][68];
    __shared__ __align__(16) float Bs[16][68];

    int tid = threadIdx.x;
    int tx = tid & 15, ty = tid >> 4;
    int m0 = blockIdx.y * 64, n0 = blockIdx.x * 64;

    int a_row = tid & 63;
    int a_k4  = (tid >> 6) * 4;
    int b_k   = tid >> 4;
    int b_n4  = (tid & 15) * 4;

    const float* Ap = z + (size_t)(m0 + a_row) * D_N + a_k4;
    const float* Bp = g_Afin + (size_t)b_k * AFIN_N + n0 + b_n4;

    unsigned long long acc[4][2];
#pragma unroll
    for (int i = 0; i < 4; i++) { acc[i][0] = 0ull; acc[i][1] = 0ull; }

    for (int k0 = 0; k0 < D_N; k0 += 16) {
        float4 av = *(const float4*)(Ap + k0);
        float4 mv = *(const float4*)(g_means + k0 + a_k4);
        float4 bv = *(const float4*)(Bp + (size_t)k0 * AFIN_N);
        av.x -= mv.x; av.y -= mv.y; av.z -= mv.z; av.w -= mv.w;
        __syncthreads();
        As[a_k4 + 0][a_row] = av.x;
        As[a_k4 + 1][a_row] = av.y;
        As[a_k4 + 2][a_row] = av.z;
        As[a_k4 + 3][a_row] = av.w;
        *(float4*)&Bs[b_k][b_n4] = bv;
        __syncthreads();
#pragma unroll
        for (int kk = 0; kk < 16; kk++) {
            float4 a = *(const float4*)&As[kk][ty * 4];
            ulonglong2 b = *(const ulonglong2*)&Bs[kk][tx * 4];
            unsigned long long a2[4];
            a2[0] = bcast2(a.x); a2[1] = bcast2(a.y);
            a2[2] = bcast2(a.z); a2[3] = bcast2(a.w);
#pragma unroll
            for (int i = 0; i < 4; i++) {
                fma2(acc[i][0], a2[i], b.x);
                fma2(acc[i][1], a2[i], b.y);
            }
        }
    }
#pragma unroll
    for (int jp = 0; jp < 2; jp++) {
        int ne = n0 + tx * 4 + 2 * jp;
#pragma unroll
        for (int i = 0; i < 4; i++) {
            float2 p = unpk2(acc[i][jp]);
            int m = m0 + ty * 4 + i;
            g_u2t[(size_t)ne * B_N + m]       = p.x;
            g_u2t[(size_t)(ne + 1) * B_N + m] = p.y;
        }
    }
}

/* ------------------------------------------------------------------ */
/* ECF slice loss                                                     */
/* ------------------------------------------------------------------ */
__device__ __forceinline__ void ecf_sample(float x, float ar[8], float ai[8]) {
    float s1, c1;
    __sincosf(x, &s1, &c1);
    float twoc = c1 + c1;
    float cm = 1.f, sm = 0.f;
    float c = c1, s = s1;
#pragma unroll
    for (int j = 0; j < 8; j++) {
        ar[j] += c; ai[j] += s;
        float cn = fmaf(twoc, c, -cm);
        float sn = fmaf(twoc, s, -sm);
        cm = c; sm = s; c = cn; s = sn;
    }
}

__global__ void __launch_bounds__(256) ecf_kernel(int which) {
    const float*  __restrict__ ut = which ? g_u2t : g_ut;
    double*       __restrict__ L  = which ? g_floss : g_losses;
    int a = blockIdx.x;
    int t = threadIdx.x;
    int lane = t & 31, warp = t >> 5;
    const float4* row4 = (const float4*)(ut + (size_t)a * B_N);

    float ar[8], ai[8];
#pragma unroll
    for (int j = 0; j < 8; j++) { ar[j] = 0.f; ai[j] = 0.f; }

#pragma unroll
    for (int it = 0; it < 2; it++) {
        float4 xv = row4[t + 256 * it];
        ecf_sample(0.625f * xv.x, ar, ai);
        ecf_sample(0.625f * xv.y, ar, ai);
        ecf_sample(0.625f * xv.z, ar, ai);
        ecf_sample(0.625f * xv.w, ar, ai);
    }

    __shared__ float2 sred[8][16];
    __shared__ double sredd[16];
#pragma unroll
    for (int q = 0; q < 16; q++) {
        float hi = (q < 8) ? ar[q] : ai[q - 8];
        float lo = 0.f;
#pragma unroll
        for (int o = 16; o; o >>= 1) {
            float h2 = __shfl_xor_sync(0xffffffffu, hi, o);
            float l2 = __shfl_xor_sync(0xffffffffu, lo, o);
            ff_add(hi, lo, h2, l2);
        }
        if (lane == 0) sred[warp][q] = make_float2(hi, lo);
    }
    __syncthreads();
    if (t < 16) {
        double tot = 0.0;
        for (int w = 0; w < 8; w++) {
            float2 p = sred[w][t];
            tot += (double)p.x + (double)p.y;
        }
        sredd[t] = tot;
    }
    __syncthreads();
    if (t == 0) {
        const double invB = 1.0 / 2048.0;
        double loss = 0.0;
#pragma unroll
        for (int j = 1; j <= 8; j++) {
            double tj = 0.625 * (double)j;
            double ph = exp(-0.5 * tj * tj);
            double re = sredd[j - 1] * invB - ph;
            double im = sredd[8 + j - 1] * invB;
            double integ = (re * re + im * im) * ph;
            loss += ((j == 8) ? 0.625 : 1.25) * integ;
        }
        L[a] = loss;
    }
}

/* ------------------------------------------------------------------ */
/* Bitonic sort                                                       */
/* ------------------------------------------------------------------ */
__global__ void __launch_bounds__(1024) sort_kernel() {
    __shared__ long long sv[2048];
    __shared__ int       si[2048];
    int t = threadIdx.x;
    for (int i = t; i < 2048; i += 1024) {
        sv[i] = __double_as_longlong(g_losses[i]);
        si[i] = i;
    }
    __syncthreads();
    for (int k = 2; k <= 2048; k <<= 1) {
        for (int jj = k >> 1; jj > 0; jj >>= 1) {
            for (int i = t; i < 2048; i += 1024) {
                int ixj = i ^ jj;
                if (ixj > i) {
                    long long va = sv[i], vb = sv[ixj];
                    int       ia = si[i], ib = si[ixj];
                    bool aFirst = (va > vb) || (va == vb && ia < ib);
                    bool dirAsc = ((i & k) == 0);
                    if (aFirst != dirAsc) {
                        sv[i] = vb; sv[ixj] = va;
                        si[i] = ib; si[ixj] = ia;
                    }
                }
            }
            __syncthreads();
        }
    }
    for (int i = t; i < HARD_N; i += 1024) g_ranked[i] = si[i];
}

/* ------------------------------------------------------------------ */
/* GS via Cholesky                                                    */
/* ------------------------------------------------------------------ */
__global__ void gather_kernel() {
    int idx = blockIdx.x * 256 + threadIdx.x;
    int i = idx >> 10, d = idx & 1023;
    g_H[idx] = g_Apool[(size_t)d * POOL_N + g_ranked[i]];
}

__global__ void __launch_bounds__(256) syrk_kernel() {
    int i = blockIdx.x;
    __shared__ float hi[D_N];
    int tid = threadIdx.x;
    *(float4*)&hi[tid * 4] = *(const float4*)&g_H[(size_t)i * D_N + tid * 4];
    __syncthreads();
    int lane = tid & 31, warp = tid >> 5;
    const float4* hi4 = (const float4*)hi;
    for (int j = warp; j < HARD_N; j += 8) {
        const float4* hj = (const float4*)&g_H[(size_t)j * D_N];
        float acc = 0.f;
        for (int d4 = lane; d4 < 256; d4 += 32) {
            float4 a = hi4[d4];
            float4 b = hj[d4];
            acc = fmaf(a.x, b.x, fmaf(a.y, b.y, fmaf(a.z, b.z, fmaf(a.w, b.w, acc))));
        }
#pragma unroll
        for (int o = 16; o; o >>= 1) acc += __shfl_down_sync(0xffffffffu, acc, o);
        if (lane == 0) g_G[i * HARD_N + j] = acc;
    }
}

/* single block, 128 threads; ILP-unrolled inner loops                */
__global__ void __launch_bounds__(128) cholinv_kernel() {
    extern __shared__ float sbuf[];
    float* sR = sbuf;
    float* sT = sbuf + HARD_N * HARD_N;
    int m = threadIdx.x;
    __shared__ float sdiag;

    for (int k = 0; k < HARD_N; k++) {
        sR[k * HARD_N + m] = g_G[k * HARD_N + m];
        sT[k * HARD_N + m] = 0.f;
    }
    __syncthreads();

    /* Cholesky: R upper-tri, G = R^T R; 8 independent accumulators */
    for (int j = 0; j < HARD_N; j++) {
        float s[8];
#pragma unroll
        for (int u = 0; u < 8; u++) s[u] = 0.f;
        int k = 0;
        for (; k + 8 <= j; k += 8) {
#pragma unroll
            for (int u = 0; u < 8; u++)
                s[u] = fmaf(sR[(k + u) * HARD_N + j], sR[(k + u) * HARD_N + m], s[u]);
        }
        for (int u = 0; k < j; k++, u++)
            s[u] = fmaf(sR[k * HARD_N + j], sR[k * HARD_N + m], s[u]);
        float smm = ((s[0] + s[1]) + (s[2] + s[3])) + ((s[4] + s[5]) + (s[6] + s[7]));
        if (m == j) {
            float dd = sR[j * HARD_N + j] - smm;
            float r  = sqrtf(fmaxf(dd, 0.f));
            sdiag = fmaxf(r, 1e-12f);
        }
        __syncthreads();
        float rjj = sdiag;
        if (m > j)       sR[j * HARD_N + m] = (sR[j * HARD_N + m] - smm) / rjj;
        else if (m == j) sR[j * HARD_N + j] = rjj;
        __syncthreads();
    }

    /* T = R^{-1}: thread m owns column m; 4 accumulators */
    int jc = m;
    sT[jc * HARD_N + jc] = 1.f / sR[jc * HARD_N + jc];
    for (int i = HARD_N - 2; i >= 0; i--) {
        float a[4];
#pragma unroll
        for (int u = 0; u < 4; u++) a[u] = 0.f;
        int k = i + 1;
        for (; k + 4 <= HARD_N; k += 4) {
#pragma unroll
            for (int u = 0; u < 4; u++)
                a[u] = fmaf(sR[i * HARD_N + k + u], sT[(k + u) * HARD_N + jc], a[u]);
        }
        for (int u = 0; k < HARD_N; k++, u++)
            a[u] = fmaf(sR[i * HARD_N + k], sT[k * HARD_N + jc], a[u]);
        float tot = (a[0] + a[1]) + (a[2] + a[3]);
        if (i < jc) sT[i * HARD_N + jc] = -tot / sR[i * HARD_N + i];
    }
    __syncthreads();
    for (int k = 0; k < HARD_N; k++)
        g_T[k * HARD_N + m] = sT[k * HARD_N + m];
}

__global__ void __launch_bounds__(256) qht_kernel() {
    int j = threadIdx.x & 127;
    int d = blockIdx.x * 2 + (threadIdx.x >> 7);
    float a0 = 0.f, a1 = 0.f;
    for (int k = 0; k < HARD_N; k += 2) {
        float h0 = g_H[(size_t)k * D_N + d];
        float h1 = g_H[(size_t)(k + 1) * D_N + d];
        a0 = fmaf(h0, g_T[k * HARD_N + j], a0);
        a1 = fmaf(h1, g_T[(k + 1) * HARD_N + j], a1);
    }
    g_Q[(size_t)j * D_N + d] = a0 + a1;
}

/* ------------------------------------------------------------------ */
/* Extra directions                                                   */
/* ------------------------------------------------------------------ */
__global__ void qtr_kernel() {
    int i = blockIdx.x;
    int j = threadIdx.x;
    const float* q = g_Q + (size_t)i * D_N;
    float s = 0.f;
    for (int d = 0; d < D_N; d++)
        s = fmaf(q[d], g_R[(size_t)d * EXTRA_N + j], s);
    g_C[i * EXTRA_N + j] = s;
}

__global__ void subproj_kernel() {
    int idx = blockIdx.x * blockDim.x + threadIdx.x;
    int d = idx >> 6, j = idx & 63;
    float s = 0.f;
    for (int i = 0; i < HARD_N; i++)
        s = fmaf(g_Q[(size_t)i * D_N + d], g_C[i * EXTRA_N + j], s);
    g_R[idx] -= s;
}

__global__ void assemble_kernel() {
    int idx = blockIdx.x * blockDim.x + threadIdx.x;
    int d = idx >> 8, c = idx & 255;
    float v = 0.f;
    if (c < HARD_N)      v = g_Q[(size_t)c * D_N + d];
    else if (c < NFIN)   v = g_R[(size_t)d * EXTRA_N + (c - HARD_N)];
    g_Afin[idx] = v;
}

__global__ void final_kernel(float* __restrict__ out) {
    __shared__ double sh[256];
    int t = threadIdx.x;
    sh[t] = (t < NFIN) ? g_floss[t] : 0.0;
    __syncthreads();
    if (t == 0) {
        double s = 0.0;
        for (int i = 0; i < NFIN; i++) s += sh[i];
        out[0] = (float)((s / 192.0) * 2048.0);
    }
}

/* ------------------------------------------------------------------ */
extern "C" void kernel_launch(void* const* d_in, const int* in_sizes, int n_in,
                              void* d_out, int out_size) {
    const float* z; const int* seed;
    if (in_sizes[0] == 1) { seed = (const int*)d_in[0]; z = (const float*)d_in[1]; }
    else                  { z = (const float*)d_in[0]; seed = (const int*)d_in[1]; }
    float* out = (float*)d_out;

    static int smem_set = 0;
    if (!smem_set) {
        cudaFuncSetAttribute(cholinv_kernel,
                             cudaFuncAttributeMaxDynamicSharedMemorySize,
                             2 * HARD_N * HARD_N * (int)sizeof(float));
        smem_set = 1;
    }

    setup_kernel<<<SETUP_POOL_BLKS + SETUP_CM_BLKS + SETUP_EXTRA_BLKS, 256>>>(z, seed);
    norm_comb_kernel<<<33, dim3(64, 16)>>>();

    gemm0_kernel<<<dim3(POOL_N / BN, B_N / BM), 512>>>(z);
    ecf_kernel<<<POOL_N, 256>>>(0);

    sort_kernel<<<1, 1024>>>();

    gather_kernel<<<(HARD_N * D_N) / 256, 256>>>();
    syrk_kernel<<<HARD_N, 256>>>();
    cholinv_kernel<<<1, 128, 2 * HARD_N * HARD_N * sizeof(float)>>>();
    qht_kernel<<<D_N / 2, 256>>>();

    qtr_kernel<<<HARD_N, EXTRA_N>>>();
    subproj_kernel<<<(D_N * EXTRA_N) / 256, 256>>>();
    norm_cols_kernel<<<1, dim3(64, 16)>>>(1);

    assemble_kernel<<<(D_N * AFIN_N) / 256, 256>>>();
    gemm1_kernel<<<dim3(NFIN / 64, B_N / 64), 256>>>(z);
    ecf_kernel<<<NFIN, 256>>>(1);

    final_kernel<<<1, 256>>>(out);
}

// round 13
// speedup vs baseline: 4.8252x; 1.0445x over previous
#include <cuda_runtime.h>
#include <stdint.h>

#define B_N    2048
#define D_N    1024
#define POOL_N 2048
#define HARD_N 128
#define EXTRA_N 64
#define AFIN_N 256
#define NFIN   192

#define BM 256
#define BN 128

/* ------------------------------------------------------------------ */
/* Scratch                                                            */
/* ------------------------------------------------------------------ */
__device__ float  g_Apool[D_N * POOL_N];
__device__ float  g_means[D_N];
__device__ float  g_ut[POOL_N * B_N];
__device__ float  g_u2t[AFIN_N * B_N];
__device__ double g_losses[POOL_N];
__device__ int    g_ranked[HARD_N];
__device__ float  g_H[HARD_N * D_N];
__device__ float  g_G[HARD_N * HARD_N];
__device__ float  g_T[HARD_N * HARD_N];
__device__ float  g_Q[HARD_N * D_N];
__device__ float  g_R[D_N * EXTRA_N];
__device__ float  g_C[HARD_N * EXTRA_N];
__device__ float  g_Afin[D_N * AFIN_N];
__device__ double g_floss[NFIN];

/* ---------------- packed f32x2 helpers ---------------------------- */
__device__ __forceinline__ unsigned long long bcast2(float x) {
    unsigned long long r;
    asm("mov.b64 %0, {%1, %1};" : "=l"(r) : "f"(x));
    return r;
}
__device__ __forceinline__ void fma2(unsigned long long& d,
                                     unsigned long long a,
                                     unsigned long long b) {
    asm("fma.rn.f32x2 %0, %1, %2, %0;" : "+l"(d) : "l"(a), "l"(b));
}
__device__ __forceinline__ float2 unpk2(unsigned long long v) {
    float2 r;
    asm("mov.b64 {%0, %1}, %2;" : "=f"(r.x), "=f"(r.y) : "l"(v));
    return r;
}

/* ------------------------------------------------------------------ */
/* JAX threefry2x32 (partitionable)                                   */
/* ------------------------------------------------------------------ */
__device__ __forceinline__ uint32_t rotl32(uint32_t x, int r) {
    return (x << r) | (x >> (32 - r));
}
__device__ __forceinline__ void threefry2x32(uint32_t k0, uint32_t k1,
                                             uint32_t x0, uint32_t x1,
                                             uint32_t& o0, uint32_t& o1) {
    uint32_t ks2 = k0 ^ k1 ^ 0x1BD11BDAu;
    x0 += k0; x1 += k1;
#define TFR(r) { x0 += x1; x1 = rotl32(x1, (r)); x1 ^= x0; }
    TFR(13) TFR(15) TFR(26) TFR(6)  x0 += k1;  x1 += ks2 + 1u;
    TFR(17) TFR(29) TFR(16) TFR(24) x0 += ks2; x1 += k0  + 2u;
    TFR(13) TFR(15) TFR(26) TFR(6)  x0 += k0;  x1 += k1  + 3u;
    TFR(17) TFR(29) TFR(16) TFR(24) x0 += k1;  x1 += ks2 + 4u;
    TFR(13) TFR(15) TFR(26) TFR(6)  x0 += ks2; x1 += k0  + 5u;
#undef TFR
    o0 = x0; o1 = x1;
}
__device__ __forceinline__ float erfinv_xla(float x) {
    float w = -log1pf(-x * x);
    float p;
    if (w < 5.0f) {
        w -= 2.5f;
        p = 2.81022636e-08f;
        p = fmaf(p, w, 3.43273939e-07f);
        p = fmaf(p, w, -3.5233877e-06f);
        p = fmaf(p, w, -4.39150654e-06f);
        p = fmaf(p, w, 0.00021858087f);
        p = fmaf(p, w, -0.00125372503f);
        p = fmaf(p, w, -0.00417768164f);
        p = fmaf(p, w, 0.246640727f);
        p = fmaf(p, w, 1.50140941f);
    } else {
        w = sqrtf(w) - 3.0f;
        p = -0.000200214257f;
        p = fmaf(p, w, 0.000100950558f);
        p = fmaf(p, w, 0.00134934322f);
        p = fmaf(p, w, -0.00367342844f);
        p = fmaf(p, w, 0.00573950773f);
        p = fmaf(p, w, -0.0076224613f);
        p = fmaf(p, w, 0.00943887047f);
        p = fmaf(p, w, 1.00167406f);
        p = fmaf(p, w, 2.83297682f);
    }
    return p * x;
}
__device__ __forceinline__ float bits_to_normal(uint32_t b) {
    float f = __uint_as_float((b >> 9) | 0x3f800000u) - 1.0f;
    const float minv = -0.99999994f;
    float u = fmaf(f, 2.0f, minv);
    u = fmaxf(u, minv);
    return 1.41421356f * erfinv_xla(u);
}

/* ------------------------------------------------------------------ */
/* Fused setup: pool gen, colmean, extra gen (R11 version)            */
/* ------------------------------------------------------------------ */
#define SETUP_POOL_BLKS  (D_N * POOL_N / 256)
#define SETUP_CM_BLKS    16
#define SETUP_EXTRA_BLKS (D_N * EXTRA_N / 256)

__global__ void __launch_bounds__(256) setup_kernel(const float* __restrict__ z,
                                                    const int* __restrict__ seed_ptr) {
    int b = blockIdx.x;
    if (b < SETUP_POOL_BLKS) {
        int i = b * 256 + threadIdx.x;
        uint32_t k1 = (uint32_t)seed_ptr[0];
        uint32_t o0, o1;
        threefry2x32(0u, k1, 0u, (uint32_t)i, o0, o1);
        g_Apool[i] = bits_to_normal(o0 ^ o1);
    } else if (b < SETUP_POOL_BLKS + SETUP_CM_BLKS) {
        __shared__ float2 sm[4][64];
        int xb = b - SETUP_POOL_BLKS;
        int x = threadIdx.x & 63, y = threadIdx.x >> 6;
        int c = xb * 64 + x;
        float s = 0.f, comp = 0.f;
        for (int r = y; r < B_N; r += 4) {
            float v = z[(size_t)r * D_N + c];
            float yv = v - comp;
            float t = s + yv;
            comp = (t - s) - yv;
            s = t;
        }
        sm[y][x] = make_float2(s, comp);
        __syncthreads();
        if (y == 0) {
            double tot = 0.0;
            for (int w = 0; w < 4; w++) {
                float2 p = sm[w][x];
                tot += (double)p.x - (double)p.y;
            }
            g_means[c] = (float)(tot * (1.0 / 2048.0));
        }
    } else {
        int i = (b - SETUP_POOL_BLKS - SETUP_CM_BLKS) * 256 + threadIdx.x;
        uint32_t k1 = (uint32_t)(seed_ptr[0] + 9991);
        uint32_t o0, o1;
        threefry2x32(0u, k1, 0u, (uint32_t)i, o0, o1);
        g_R[i] = bits_to_normal(o0 ^ o1);
    }
}

/* ------------------------------------------------------------------ */
/* Column normalize (R11 version)                                     */
/* ------------------------------------------------------------------ */
__device__ __forceinline__ void norm_cols_body(float* A, int nc, int col) {
    __shared__ float2 sm[16][64];
    __shared__ float sden[64];
    int x = threadIdx.x, y = threadIdx.y;
    float s = 0.f, comp = 0.f;
    for (int r = 0; r < 64; r++) {
        int d = y * 64 + r;
        float v = A[(size_t)d * nc + col];
        float v2 = v * v;
        float yv = v2 - comp;
        float t = s + yv;
        comp = (t - s) - yv;
        s = t;
    }
    sm[y][x] = make_float2(s, comp);
    __syncthreads();
    if (y == 0) {
        double tot = 0.0;
        for (int w = 0; w < 16; w++) {
            float2 p = sm[w][x];
            tot += (double)p.x - (double)p.y;
        }
        sden[x] = (float)sqrt(tot) + 1e-12f;
    }
    __syncthreads();
    float den = sden[x];
    for (int r = 0; r < 64; r++) {
        int d = y * 64 + r;
        A[(size_t)d * nc + col] /= den;
    }
}

__global__ void norm_comb_kernel() {
    if (blockIdx.x < 32)
        norm_cols_body(g_Apool, POOL_N, blockIdx.x * 64 + threadIdx.x);
    else
        norm_cols_body(g_R, EXTRA_N, threadIdx.x);
}

__global__ void norm_cols_kernel(int which) {
    float* A = which ? g_R : g_Apool;
    int nc   = which ? EXTRA_N : POOL_N;
    norm_cols_body(A, nc, blockIdx.x * 64 + threadIdx.x);
}

/* ------------------------------------------------------------------ */
/* GEMM0 (R11 version): 256x128, 512 thr, f32x2, double-buffered      */
/* ------------------------------------------------------------------ */
__global__ void __launch_bounds__(512, 1) gemm0_kernel(const float* __restrict__ z) {
    __shared__ __align__(16) float As[2][8][BM + 4];
    __shared__ __align__(16) float Bs[2][8][BN + 4];

    int tid = threadIdx.x;
    int tx = tid & 15;
    int ty = tid >> 4;
    int m0 = blockIdx.y * BM, n0 = blockIdx.x * BN;

    int a_row = tid >> 1;
    int a_k4  = (tid & 1) * 4;
    int b_k   = tid >> 6;
    int b_n2  = (tid & 63) * 2;

    const float* Ap = z + (size_t)(m0 + a_row) * D_N + a_k4;
    const float* Bp = g_Apool + (size_t)b_k * POOL_N + n0 + b_n2;

    unsigned long long acc[8][4];
#pragma unroll
    for (int i = 0; i < 8; i++)
#pragma unroll
        for (int jp = 0; jp < 4; jp++) acc[i][jp] = 0ull;

    float4 av = *(const float4*)Ap;
    float4 mv = *(const float4*)(g_means + a_k4);
    float2 bv = *(const float2*)Bp;

    for (int c = 0; c < D_N / 8; c++) {
        int buf = c & 1;
        As[buf][a_k4 + 0][a_row] = av.x - mv.x;
        As[buf][a_k4 + 1][a_row] = av.y - mv.y;
        As[buf][a_k4 + 2][a_row] = av.z - mv.z;
        As[buf][a_k4 + 3][a_row] = av.w - mv.w;
        *(float2*)&Bs[buf][b_k][b_n2] = bv;
        __syncthreads();
        if (c + 1 < D_N / 8) {
            int k0 = (c + 1) * 8;
            av = *(const float4*)(Ap + k0);
            mv = *(const float4*)(g_means + k0 + a_k4);
            bv = *(const float2*)(Bp + (size_t)k0 * POOL_N);
        }
#pragma unroll
        for (int kk = 0; kk < 8; kk++) {
            float4 a0 = *(const float4*)&As[buf][kk][ty * 8];
            float4 a1 = *(const float4*)&As[buf][kk][ty * 8 + 4];
            ulonglong2 b0 = *(const ulonglong2*)&Bs[buf][kk][tx * 8];
            ulonglong2 b1 = *(const ulonglong2*)&Bs[buf][kk][tx * 8 + 4];
            unsigned long long a2[8];
            a2[0] = bcast2(a0.x); a2[1] = bcast2(a0.y);
            a2[2] = bcast2(a0.z); a2[3] = bcast2(a0.w);
            a2[4] = bcast2(a1.x); a2[5] = bcast2(a1.y);
            a2[6] = bcast2(a1.z); a2[7] = bcast2(a1.w);
#pragma unroll
            for (int i = 0; i < 8; i++) {
                fma2(acc[i][0], a2[i], b0.x);
                fma2(acc[i][1], a2[i], b0.y);
                fma2(acc[i][2], a2[i], b1.x);
                fma2(acc[i][3], a2[i], b1.y);
            }
        }
    }

#pragma unroll
    for (int jp = 0; jp < 4; jp++) {
        float lo[8], hi[8];
#pragma unroll
        for (int i = 0; i < 8; i++) {
            float2 p = unpk2(acc[i][jp]);
            lo[i] = p.x; hi[i] = p.y;
        }
        int ne = n0 + tx * 8 + 2 * jp;
        float* be = &g_ut[(size_t)ne * B_N + m0 + ty * 8];
        float* bo = &g_ut[(size_t)(ne + 1) * B_N + m0 + ty * 8];
        *(float4*)be       = make_float4(lo[0], lo[1], lo[2], lo[3]);
        *(float4*)(be + 4) = make_float4(lo[4], lo[5], lo[6], lo[7]);
        *(float4*)bo       = make_float4(hi[0], hi[1], hi[2], hi[3]);
        *(float4*)(bo + 4) = make_float4(hi[4], hi[5], hi[6], hi[7]);
    }
}

/* ------------------------------------------------------------------ */
/* GEMM1 (final): 64x64 tiles, f32x2                                  */
/* ------------------------------------------------------------------ */
__global__ void __launch_bounds__(256) gemm1_kernel(const float* __restrict__ z) {
    __shared__ __align__(16) float As[16][68];
    __shared__ __align__(16) float Bs[16][68];

    int tid = threadIdx.x;
    int tx = tid & 15, ty = tid >> 4;
    int m0 = blockIdx.y * 64, n0 = blockIdx.x * 64;

    int a_row = tid & 63;
    int a_k4  = (tid >> 6) * 4;
    int b_k   = tid >> 4;
    int b_n4  = (tid & 15) * 4;

    const float* Ap = z + (size_t)(m0 + a_row) * D_N + a_k4;
    const float* Bp = g_Afin + (size_t)b_k * AFIN_N + n0 + b_n4;

    unsigned long long acc[4][2];
#pragma unroll
    for (int i = 0; i < 4; i++) { acc[i][0] = 0ull; acc[i][1] = 0ull; }

    for (int k0 = 0; k0 < D_N; k0 += 16) {
        float4 av = *(const float4*)(Ap + k0);
        float4 mv = *(const float4*)(g_means + k0 + a_k4);
        float4 bv = *(const float4*)(Bp + (size_t)k0 * AFIN_N);
        av.x -= mv.x; av.y -= mv.y; av.z -= mv.z; av.w -= mv.w;
        __syncthreads();
        As[a_k4 + 0][a_row] = av.x;
        As[a_k4 + 1][a_row] = av.y;
        As[a_k4 + 2][a_row] = av.z;
        As[a_k4 + 3][a_row] = av.w;
        *(float4*)&Bs[b_k][b_n4] = bv;
        __syncthreads();
#pragma unroll
        for (int kk = 0; kk < 16; kk++) {
            float4 a = *(const float4*)&As[kk][ty * 4];
            ulonglong2 b = *(const ulonglong2*)&Bs[kk][tx * 4];
            unsigned long long a2[4];
            a2[0] = bcast2(a.x); a2[1] = bcast2(a.y);
            a2[2] = bcast2(a.z); a2[3] = bcast2(a.w);
#pragma unroll
            for (int i = 0; i < 4; i++) {
                fma2(acc[i][0], a2[i], b.x);
                fma2(acc[i][1], a2[i], b.y);
            }
        }
    }
#pragma unroll
    for (int jp = 0; jp < 2; jp++) {
        int ne = n0 + tx * 4 + 2 * jp;
#pragma unroll
        for (int i = 0; i < 4; i++) {
            float2 p = unpk2(acc[i][jp]);
            int m = m0 + ty * 4 + i;
            g_u2t[(size_t)ne * B_N + m]       = p.x;
            g_u2t[(size_t)(ne + 1) * B_N + m] = p.y;
        }
    }
}

/* ------------------------------------------------------------------ */
/* ECF slice loss: plain f32 butterflies, f64 across warps (CHANGED)  */
/* ------------------------------------------------------------------ */
__device__ __forceinline__ void ecf_sample(float x, float ar[8], float ai[8]) {
    float s1, c1;
    __sincosf(x, &s1, &c1);
    float twoc = c1 + c1;
    float cm = 1.f, sm = 0.f;
    float c = c1, s = s1;
#pragma unroll
    for (int j = 0; j < 8; j++) {
        ar[j] += c; ai[j] += s;
        float cn = fmaf(twoc, c, -cm);
        float sn = fmaf(twoc, s, -sm);
        cm = c; sm = s; c = cn; s = sn;
    }
}

__global__ void __launch_bounds__(256) ecf_kernel(int which) {
    const float*  __restrict__ ut = which ? g_u2t : g_ut;
    double*       __restrict__ L  = which ? g_floss : g_losses;
    int a = blockIdx.x;
    int t = threadIdx.x;
    int lane = t & 31, warp = t >> 5;
    const float4* row4 = (const float4*)(ut + (size_t)a * B_N);

    float ar[8], ai[8];
#pragma unroll
    for (int j = 0; j < 8; j++) { ar[j] = 0.f; ai[j] = 0.f; }

#pragma unroll
    for (int it = 0; it < 2; it++) {
        float4 xv = row4[t + 256 * it];
        ecf_sample(0.625f * xv.x, ar, ai);
        ecf_sample(0.625f * xv.y, ar, ai);
        ecf_sample(0.625f * xv.z, ar, ai);
        ecf_sample(0.625f * xv.w, ar, ai);
    }

    __shared__ float sred[8][16];
    __shared__ double sredd[16];
#pragma unroll
    for (int q = 0; q < 16; q++) {
        float v = (q < 8) ? ar[q] : ai[q - 8];
#pragma unroll
        for (int o = 16; o; o >>= 1) v += __shfl_xor_sync(0xffffffffu, v, o);
        if (lane == 0) sred[warp][q] = v;
    }
    __syncthreads();
    if (t < 16) {
        double tot = 0.0;
        for (int w = 0; w < 8; w++) tot += (double)sred[w][t];
        sredd[t] = tot;
    }
    __syncthreads();
    if (t == 0) {
        const double invB = 1.0 / 2048.0;
        double loss = 0.0;
#pragma unroll
        for (int j = 1; j <= 8; j++) {
            double tj = 0.625 * (double)j;
            double ph = exp(-0.5 * tj * tj);
            double re = sredd[j - 1] * invB - ph;
            double im = sredd[8 + j - 1] * invB;
            double integ = (re * re + im * im) * ph;
            loss += ((j == 8) ? 0.625 : 1.25) * integ;
        }
        L[a] = loss;
    }
}

/* ------------------------------------------------------------------ */
/* Bitonic sort                                                       */
/* ------------------------------------------------------------------ */
__global__ void __launch_bounds__(1024) sort_kernel() {
    __shared__ long long sv[2048];
    __shared__ int       si[2048];
    int t = threadIdx.x;
    for (int i = t; i < 2048; i += 1024) {
        sv[i] = __double_as_longlong(g_losses[i]);
        si[i] = i;
    }
    __syncthreads();
    for (int k = 2; k <= 2048; k <<= 1) {
        for (int jj = k >> 1; jj > 0; jj >>= 1) {
            for (int i = t; i < 2048; i += 1024) {
                int ixj = i ^ jj;
                if (ixj > i) {
                    long long va = sv[i], vb = sv[ixj];
                    int       ia = si[i], ib = si[ixj];
                    bool aFirst = (va > vb) || (va == vb && ia < ib);
                    bool dirAsc = ((i & k) == 0);
                    if (aFirst != dirAsc) {
                        sv[i] = vb; sv[ixj] = va;
                        si[i] = ib; si[ixj] = ia;
                    }
                }
            }
            __syncthreads();
        }
    }
    for (int i = t; i < HARD_N; i += 1024) g_ranked[i] = si[i];
}

/* ------------------------------------------------------------------ */
/* GS via Cholesky                                                    */
/* ------------------------------------------------------------------ */
__global__ void gather_kernel() {
    int idx = blockIdx.x * 256 + threadIdx.x;
    int i = idx >> 10, d = idx & 1023;
    g_H[idx] = g_Apool[(size_t)d * POOL_N + g_ranked[i]];
}

__global__ void __launch_bounds__(256) syrk_kernel() {
    int i = blockIdx.x;
    __shared__ float hi[D_N];
    int tid = threadIdx.x;
    *(float4*)&hi[tid * 4] = *(const float4*)&g_H[(size_t)i * D_N + tid * 4];
    __syncthreads();
    int lane = tid & 31, warp = tid >> 5;
    const float4* hi4 = (const float4*)hi;
    for (int j = warp; j < HARD_N; j += 8) {
        const float4* hj = (const float4*)&g_H[(size_t)j * D_N];
        float acc = 0.f;
        for (int d4 = lane; d4 < 256; d4 += 32) {
            float4 a = hi4[d4];
            float4 b = hj[d4];
            acc = fmaf(a.x, b.x, fmaf(a.y, b.y, fmaf(a.z, b.z, fmaf(a.w, b.w, acc))));
        }
#pragma unroll
        for (int o = 16; o; o >>= 1) acc += __shfl_down_sync(0xffffffffu, acc, o);
        if (lane == 0) g_G[i * HARD_N + j] = acc;
    }
}

__global__ void __launch_bounds__(128) cholinv_kernel() {
    extern __shared__ float sbuf[];
    float* sR = sbuf;
    float* sT = sbuf + HARD_N * HARD_N;
    int m = threadIdx.x;
    __shared__ float sdiag;

    for (int k = 0; k < HARD_N; k++) {
        sR[k * HARD_N + m] = g_G[k * HARD_N + m];
        sT[k * HARD_N + m] = 0.f;
    }
    __syncthreads();

    for (int j = 0; j < HARD_N; j++) {
        float s[8];
#pragma unroll
        for (int u = 0; u < 8; u++) s[u] = 0.f;
        int k = 0;
        for (; k + 8 <= j; k += 8) {
#pragma unroll
            for (int u = 0; u < 8; u++)
                s[u] = fmaf(sR[(k + u) * HARD_N + j], sR[(k + u) * HARD_N + m], s[u]);
        }
        for (int u = 0; k < j; k++, u++)
            s[u] = fmaf(sR[k * HARD_N + j], sR[k * HARD_N + m], s[u]);
        float smm = ((s[0] + s[1]) + (s[2] + s[3])) + ((s[4] + s[5]) + (s[6] + s[7]));
        if (m == j) {
            float dd = sR[j * HARD_N + j] - smm;
            float r  = sqrtf(fmaxf(dd, 0.f));
            sdiag = fmaxf(r, 1e-12f);
        }
        __syncthreads();
        float rjj = sdiag;
        if (m > j)       sR[j * HARD_N + m] = (sR[j * HARD_N + m] - smm) / rjj;
        else if (m == j) sR[j * HARD_N + j] = rjj;
        __syncthreads();
    }

    int jc = m;
    sT[jc * HARD_N + jc] = 1.f / sR[jc * HARD_N + jc];
    for (int i = HARD_N - 2; i >= 0; i--) {
        float a[4];
#pragma unroll
        for (int u = 0; u < 4; u++) a[u] = 0.f;
        int k = i + 1;
        for (; k + 4 <= HARD_N; k += 4) {
#pragma unroll
            for (int u = 0; u < 4; u++)
                a[u] = fmaf(sR[i * HARD_N + k + u], sT[(k + u) * HARD_N + jc], a[u]);
        }
        for (int u = 0; k < HARD_N; k++, u++)
            a[u] = fmaf(sR[i * HARD_N + k], sT[k * HARD_N + jc], a[u]);
        float tot = (a[0] + a[1]) + (a[2] + a[3]);
        if (i < jc) sT[i * HARD_N + jc] = -tot / sR[i * HARD_N + i];
    }
    __syncthreads();
    for (int k = 0; k < HARD_N; k++)
        g_T[k * HARD_N + m] = sT[k * HARD_N + m];
}

__global__ void __launch_bounds__(256) qht_kernel() {
    int j = threadIdx.x & 127;
    int d = blockIdx.x * 2 + (threadIdx.x >> 7);
    float a0 = 0.f, a1 = 0.f;
    for (int k = 0; k < HARD_N; k += 2) {
        float h0 = g_H[(size_t)k * D_N + d];
        float h1 = g_H[(size_t)(k + 1) * D_N + d];
        a0 = fmaf(h0, g_T[k * HARD_N + j], a0);
        a1 = fmaf(h1, g_T[(k + 1) * HARD_N + j], a1);
    }
    g_Q[(size_t)j * D_N + d] = a0 + a1;
}

/* ------------------------------------------------------------------ */
/* Extra directions: qtr (64,4) d-split (CHANGED)                     */
/* ------------------------------------------------------------------ */
__global__ void qtr_kernel() {
    __shared__ float sm[4][64];
    int i = blockIdx.x;
    int j = threadIdx.x, dq = threadIdx.y;
    const float* q = g_Q + (size_t)i * D_N + dq * 256;
    const float* r = g_R + (size_t)(dq * 256) * EXTRA_N + j;
    float s = 0.f;
#pragma unroll 4
    for (int d = 0; d < 256; d++)
        s = fmaf(q[d], r[(size_t)d * EXTRA_N], s);
    sm[dq][j] = s;
    __syncthreads();
    if (dq == 0) {
        double t = (double)sm[0][j] + (double)sm[1][j]
                 + (double)sm[2][j] + (double)sm[3][j];
        g_C[i * EXTRA_N + j] = (float)t;
    }
}

__global__ void subproj_kernel() {
    int idx = blockIdx.x * blockDim.x + threadIdx.x;
    int d = idx >> 6, j = idx & 63;
    float s = 0.f;
    for (int i = 0; i < HARD_N; i++)
        s = fmaf(g_Q[(size_t)i * D_N + d], g_C[i * EXTRA_N + j], s);
    g_R[idx] -= s;
}

__global__ void assemble_kernel() {
    int idx = blockIdx.x * blockDim.x + threadIdx.x;
    int d = idx >> 8, c = idx & 255;
    float v = 0.f;
    if (c < HARD_N)      v = g_Q[(size_t)c * D_N + d];
    else if (c < NFIN)   v = g_R[(size_t)d * EXTRA_N + (c - HARD_N)];
    g_Afin[idx] = v;
}

__global__ void final_kernel(float* __restrict__ out) {
    __shared__ double sh[256];
    int t = threadIdx.x;
    sh[t] = (t < NFIN) ? g_floss[t] : 0.0;
    __syncthreads();
    if (t == 0) {
        double s = 0.0;
        for (int i = 0; i < NFIN; i++) s += sh[i];
        out[0] = (float)((s / 192.0) * 2048.0);
    }
}

/* ------------------------------------------------------------------ */
extern "C" void kernel_launch(void* const* d_in, const int* in_sizes, int n_in,
                              void* d_out, int out_size) {
    const float* z; const int* seed;
    if (in_sizes[0] == 1) { seed = (const int*)d_in[0]; z = (const float*)d_in[1]; }
    else                  { z = (const float*)d_in[0]; seed = (const int*)d_in[1]; }
    float* out = (float*)d_out;

    static int smem_set = 0;
    if (!smem_set) {
        cudaFuncSetAttribute(cholinv_kernel,
                             cudaFuncAttributeMaxDynamicSharedMemorySize,
                             2 * HARD_N * HARD_N * (int)sizeof(float));
        smem_set = 1;
    }

    setup_kernel<<<SETUP_POOL_BLKS + SETUP_CM_BLKS + SETUP_EXTRA_BLKS, 256>>>(z, seed);
    norm_comb_kernel<<<33, dim3(64, 16)>>>();

    gemm0_kernel<<<dim3(POOL_N / BN, B_N / BM), 512>>>(z);
    ecf_kernel<<<POOL_N, 256>>>(0);

    sort_kernel<<<1, 1024>>>();

    gather_kernel<<<(HARD_N * D_N) / 256, 256>>>();
    syrk_kernel<<<HARD_N, 256>>>();
    cholinv_kernel<<<1, 128, 2 * HARD_N * HARD_N * sizeof(float)>>>();
    qht_kernel<<<D_N / 2, 256>>>();

    qtr_kernel<<<HARD_N, dim3(64, 4)>>>();
    subproj_kernel<<<(D_N * EXTRA_N) / 256, 256>>>();
    norm_cols_kernel<<<1, dim3(64, 16)>>>(1);

    assemble_kernel<<<(D_N * AFIN_N) / 256, 256>>>();
    gemm1_kernel<<<dim3(NFIN / 64, B_N / 64), 256>>>(z);
    ecf_kernel<<<NFIN, 256>>>(1);

    final_kernel<<<1, 256>>>(out);
}